// round 1
// baseline (speedup 1.0000x reference)
#include <cuda_runtime.h>
#include <math.h>

#define BATCH 8
#define NPTS  8192
#define MPTS  2048
#define C1    128
#define C2    256
#define CMID  256
#define KDIM  (C2 + C1)   // 384

// ---------------- scratch (device globals; no allocation allowed) ----------
__device__ int   g_idx[BATCH * NPTS * 3];
__device__ float g_w  [BATCH * NPTS * 3];
__device__ float g_Xi [BATCH * C2   * NPTS];   // interpolated features (67 MB)
__device__ float g_Y1 [BATCH * CMID * NPTS];   // layer-1 activations   (67 MB)

// ---------------- kernel 1: three_nn + weights ------------------------------
__global__ __launch_bounds__(256)
void three_nn_kernel(const float* __restrict__ unknown,
                     const float* __restrict__ known)
{
    __shared__ float4 sk[MPTS];            // x,y,z,|k|^2  (32 KB)
    const int b = blockIdx.y;
    const int j = blockIdx.x * blockDim.x + threadIdx.x;

    const float* kb = known + (size_t)b * MPTS * 3;
    for (int i = threadIdx.x; i < MPTS; i += blockDim.x) {
        float x = kb[i * 3 + 0], y = kb[i * 3 + 1], z = kb[i * 3 + 2];
        sk[i] = make_float4(x, y, z, x * x + y * y + z * z);
    }
    __syncthreads();

    const float* up = unknown + ((size_t)b * NPTS + j) * 3;
    const float ux = up[0], uy = up[1], uz = up[2];
    const float u2 = ux * ux + uy * uy + uz * uz;

    float d0 = 3.4e38f, d1 = 3.4e38f, d2v = 3.4e38f;
    int   i0 = 0, i1 = 0, i2 = 0;

    #pragma unroll 4
    for (int i = 0; i < MPTS; i++) {
        float4 k = sk[i];
        float dot = ux * k.x + uy * k.y + uz * k.z;
        float d = u2 + k.w - 2.0f * dot;   // match reference formula/rounding
        if (d < d0)       { d2v = d1; i2 = i1; d1 = d0; i1 = i0; d0 = d; i0 = i; }
        else if (d < d1)  { d2v = d1; i2 = i1; d1 = d;  i1 = i; }
        else if (d < d2v) { d2v = d;  i2 = i; }
    }

    float s0 = sqrtf(fmaxf(d0, 0.0f));
    float s1 = sqrtf(fmaxf(d1, 0.0f));
    float s2 = sqrtf(fmaxf(d2v, 0.0f));
    float r0 = 1.0f / (s0 + 1e-8f);
    float r1 = 1.0f / (s1 + 1e-8f);
    float r2 = 1.0f / (s2 + 1e-8f);
    float rs = r0 + r1 + r2;

    const int o = ((b * NPTS) + j) * 3;
    g_idx[o + 0] = i0; g_idx[o + 1] = i1; g_idx[o + 2] = i2;
    g_w[o + 0] = r0 / rs; g_w[o + 1] = r1 / rs; g_w[o + 2] = r2 / rs;
}

// ---------------- kernel 2: three_interpolate -> g_Xi -----------------------
// block = 256 threads = 8 warps x 32 lanes; lane -> point j, warp -> channel group
__global__ __launch_bounds__(256)
void interp_kernel(const float* __restrict__ kf)
{
    const int b    = blockIdx.y;
    const int lane = threadIdx.x & 31;
    const int warp = threadIdx.x >> 5;            // 0..7
    const int j    = blockIdx.x * 32 + lane;

    const int o = ((b * NPTS) + j) * 3;
    const int   i0 = g_idx[o + 0], i1 = g_idx[o + 1], i2 = g_idx[o + 2];
    const float w0 = g_w[o + 0],   w1 = g_w[o + 1],   w2 = g_w[o + 2];

    const float* kfb = kf   + (size_t)b * C2 * MPTS;
    float*       xb  = g_Xi + (size_t)b * C2 * NPTS;

    for (int c = warp; c < C2; c += 8) {
        const float* row = kfb + (size_t)c * MPTS;
        xb[(size_t)c * NPTS + j] = row[i0] * w0 + row[i1] * w1 + row[i2] * w2;
    }
}

// ---------------- kernel 3/4: fused GEMM + bias + ReLU ----------------------
// C[m, nBase+n] = relu( sum_k W[m,k] * B(k, n) + bias[m] )
// B(k,n): k <  Ksplit -> B0 + k*NPTS + n
//         k >= Ksplit -> B1 + (k-Ksplit)*NPTS + n
// grid: (NPTS/64, M/64, BATCH); block 256 threads; per-thread 4x4 microtile
__global__ __launch_bounds__(256)
void gemm_bias_relu(const float* __restrict__ W,
                    const float* __restrict__ bias,
                    const float* __restrict__ B0, unsigned long long strideB0,
                    const float* __restrict__ B1, unsigned long long strideB1,
                    float* __restrict__ Cout,     unsigned long long strideC,
                    int K, int Ksplit)
{
    const int BM = 64, BN = 64, BK = 16;
    __shared__ float sA[16][BM + 4];   // [k][m], padded
    __shared__ float sB[16][BN];       // [k][n]

    const int b = blockIdx.z;
    B0   += (size_t)b * strideB0;
    B1   += (size_t)b * strideB1;
    Cout += (size_t)b * strideC;

    const int mBase = blockIdx.y * BM;
    const int nBase = blockIdx.x * BN;
    const int tid = threadIdx.x;
    const int tx = tid & 15;        // n group
    const int ty = tid >> 4;        // m group

    float acc[4][4] = {};

    for (int k0 = 0; k0 < K; k0 += BK) {
        // load A tile (W): 64m x 16k
        #pragma unroll
        for (int t = 0; t < 4; t++) {
            int i = tid + t * 256;
            int k = i & 15;
            int m = i >> 4;
            sA[k][m] = W[(size_t)(mBase + m) * K + (k0 + k)];
        }
        // load B tile: 16k x 64n, split-sourced
        #pragma unroll
        for (int t = 0; t < 4; t++) {
            int i = tid + t * 256;
            int jn = i & 63;
            int k  = i >> 6;
            int kg = k0 + k;
            const float* row = (kg < Ksplit)
                ? (B0 + (size_t)kg * NPTS)
                : (B1 + (size_t)(kg - Ksplit) * NPTS);
            sB[k][jn] = row[nBase + jn];
        }
        __syncthreads();

        #pragma unroll
        for (int k = 0; k < BK; k++) {
            float a[4], bb[4];
            *(float4*)a  = *(const float4*)&sA[k][ty * 4];
            *(float4*)bb = *(const float4*)&sB[k][tx * 4];
            #pragma unroll
            for (int i = 0; i < 4; i++)
                #pragma unroll
                for (int jj = 0; jj < 4; jj++)
                    acc[i][jj] = fmaf(a[i], bb[jj], acc[i][jj]);
        }
        __syncthreads();
    }

    #pragma unroll
    for (int i = 0; i < 4; i++) {
        int m = mBase + ty * 4 + i;
        float bv = bias[m];
        float4 r;
        r.x = fmaxf(acc[i][0] + bv, 0.0f);
        r.y = fmaxf(acc[i][1] + bv, 0.0f);
        r.z = fmaxf(acc[i][2] + bv, 0.0f);
        r.w = fmaxf(acc[i][3] + bv, 0.0f);
        *(float4*)&Cout[(size_t)m * NPTS + nBase + tx * 4] = r;
    }
}

// ---------------- launch -----------------------------------------------------
extern "C" void kernel_launch(void* const* d_in, const int* in_sizes, int n_in,
                              void* d_out, int out_size)
{
    const float* unknown = (const float*)d_in[0];
    const float* known   = (const float*)d_in[1];
    const float* uf      = (const float*)d_in[2];
    const float* kf      = (const float*)d_in[3];
    const float* W1      = (const float*)d_in[4];
    const float* b1      = (const float*)d_in[5];
    const float* W2      = (const float*)d_in[6];
    const float* b2      = (const float*)d_in[7];
    float* out = (float*)d_out;

    float* p_Xi = nullptr;
    float* p_Y1 = nullptr;
    cudaGetSymbolAddress((void**)&p_Xi, g_Xi);
    cudaGetSymbolAddress((void**)&p_Y1, g_Y1);

    three_nn_kernel<<<dim3(NPTS / 256, BATCH), 256>>>(unknown, known);
    interp_kernel  <<<dim3(NPTS / 32,  BATCH), 256>>>(kf);

    // layer 1: K = 384 (256 from g_Xi, 128 directly from unknown_feats)
    gemm_bias_relu<<<dim3(NPTS / 64, CMID / 64, BATCH), 256>>>(
        W1, b1,
        p_Xi, (unsigned long long)C2 * NPTS,
        uf,   (unsigned long long)C1 * NPTS,
        p_Y1, (unsigned long long)CMID * NPTS,
        KDIM, C2);

    // layer 2: K = 256, single source
    gemm_bias_relu<<<dim3(NPTS / 64, C2 / 64, BATCH), 256>>>(
        W2, b2,
        p_Y1, (unsigned long long)CMID * NPTS,
        p_Y1, (unsigned long long)CMID * NPTS,
        out,  (unsigned long long)C2 * NPTS,
        CMID, CMID);
}

// round 2
// speedup vs baseline: 1.1484x; 1.1484x over previous
#include <cuda_runtime.h>
#include <math.h>

#define BATCH 8
#define NPTS  8192
#define MPTS  2048
#define C1    128
#define C2    256
#define CMID  256
#define KDIM  (C2 + C1)   // 384

// ---------------- scratch (device globals; no allocation allowed) ----------
__device__ int   g_idx[BATCH * NPTS * 3];
__device__ float g_w  [BATCH * NPTS * 3];
__device__ float g_Xi [BATCH * C2   * NPTS];   // interpolated features (67 MB)
__device__ float g_Y1 [BATCH * CMID * NPTS];   // layer-1 activations   (67 MB)

// ---------------- kernel 1: three_nn + weights ------------------------------
__global__ __launch_bounds__(256)
void three_nn_kernel(const float* __restrict__ unknown,
                     const float* __restrict__ known)
{
    __shared__ float4 sk[MPTS];            // x,y,z,|k|^2  (32 KB)
    const int b = blockIdx.y;
    const int j = blockIdx.x * blockDim.x + threadIdx.x;

    const float* kb = known + (size_t)b * MPTS * 3;
    for (int i = threadIdx.x; i < MPTS; i += blockDim.x) {
        float x = kb[i * 3 + 0], y = kb[i * 3 + 1], z = kb[i * 3 + 2];
        sk[i] = make_float4(x, y, z, x * x + y * y + z * z);
    }
    __syncthreads();

    const float* up = unknown + ((size_t)b * NPTS + j) * 3;
    const float ux = up[0], uy = up[1], uz = up[2];
    const float u2 = ux * ux + uy * uy + uz * uz;

    float d0 = 3.4e38f, d1 = 3.4e38f, d2v = 3.4e38f;
    int   i0 = 0, i1 = 0, i2 = 0;

    #pragma unroll 4
    for (int i = 0; i < MPTS; i++) {
        float4 k = sk[i];
        float dot = ux * k.x + uy * k.y + uz * k.z;
        float d = u2 + k.w - 2.0f * dot;   // match reference formula/rounding
        if (d < d0)       { d2v = d1; i2 = i1; d1 = d0; i1 = i0; d0 = d; i0 = i; }
        else if (d < d1)  { d2v = d1; i2 = i1; d1 = d;  i1 = i; }
        else if (d < d2v) { d2v = d;  i2 = i; }
    }

    float s0 = sqrtf(fmaxf(d0, 0.0f));
    float s1 = sqrtf(fmaxf(d1, 0.0f));
    float s2 = sqrtf(fmaxf(d2v, 0.0f));
    float r0 = 1.0f / (s0 + 1e-8f);
    float r1 = 1.0f / (s1 + 1e-8f);
    float r2 = 1.0f / (s2 + 1e-8f);
    float rs = r0 + r1 + r2;

    const int o = ((b * NPTS) + j) * 3;
    g_idx[o + 0] = i0; g_idx[o + 1] = i1; g_idx[o + 2] = i2;
    g_w[o + 0] = r0 / rs; g_w[o + 1] = r1 / rs; g_w[o + 2] = r2 / rs;
}

// ---------------- kernel 2: three_interpolate -> g_Xi -----------------------
__global__ __launch_bounds__(256)
void interp_kernel(const float* __restrict__ kf)
{
    const int b    = blockIdx.y;
    const int lane = threadIdx.x & 31;
    const int warp = threadIdx.x >> 5;            // 0..7
    const int j    = blockIdx.x * 32 + lane;

    const int o = ((b * NPTS) + j) * 3;
    const int   i0 = g_idx[o + 0], i1 = g_idx[o + 1], i2 = g_idx[o + 2];
    const float w0 = g_w[o + 0],   w1 = g_w[o + 1],   w2 = g_w[o + 2];

    const float* kfb = kf   + (size_t)b * C2 * MPTS;
    float*       xb  = g_Xi + (size_t)b * C2 * NPTS;

    for (int c = warp; c < C2; c += 8) {
        const float* row = kfb + (size_t)c * MPTS;
        xb[(size_t)c * NPTS + j] = row[i0] * w0 + row[i1] * w1 + row[i2] * w2;
    }
}

// ---------------- kernel 3/4: fused GEMM + bias + ReLU ----------------------
// C[m, n] = relu( sum_k W[m,k] * B(k, n) + bias[m] )
// B(k,n): k <  Ksplit -> B0 + k*NPTS + n ; else B1 + (k-Ksplit)*NPTS + n
// 128x128x8 block tile, 256 threads, 8x8 microtile, double-buffered smem.
#define BM 128
#define BN 128
#define BKK 8

__global__ __launch_bounds__(256)
void gemm_bias_relu(const float* __restrict__ W,
                    const float* __restrict__ bias,
                    const float* __restrict__ B0, unsigned long long strideB0,
                    const float* __restrict__ B1, unsigned long long strideB1,
                    float* __restrict__ Cout,     unsigned long long strideC,
                    int K, int Ksplit)
{
    __shared__ float sA[2][BKK][BM + 4];   // [buf][k][m]
    __shared__ float sB[2][BKK][BN];       // [buf][k][n]

    const int b = blockIdx.z;
    B0   += (size_t)b * strideB0;
    B1   += (size_t)b * strideB1;
    Cout += (size_t)b * strideC;

    const int mBase = blockIdx.y * BM;
    const int nBase = blockIdx.x * BN;
    const int tid = threadIdx.x;

    // global-load index maps
    const int am = tid >> 1;            // 0..127  (m row of W)
    const int ak = (tid & 1) * 4;       // 0 or 4  (k quad)
    const int bk = tid >> 5;            // 0..7    (k row of B)
    const int bn = (tid & 31) * 4;      // 0..124  (n quad)

    const float* Aptr = W + (size_t)(mBase + am) * K + ak;

    // compute-phase index maps
    const int tx = tid & 15;            // n group
    const int ty = tid >> 4;            // m group

    float acc[8][8] = {};
    float4 ra, rb;

    // ---- prefetch tile 0 ----
    ra = *(const float4*)(Aptr);
    {
        const float* row = (bk < Ksplit) ? (B0 + (size_t)bk * NPTS)
                                         : (B1 + (size_t)(bk - Ksplit) * NPTS);
        rb = *(const float4*)(row + nBase + bn);
    }
    sA[0][ak + 0][am] = ra.x;
    sA[0][ak + 1][am] = ra.y;
    sA[0][ak + 2][am] = ra.z;
    sA[0][ak + 3][am] = ra.w;
    *(float4*)&sB[0][bk][bn] = rb;
    __syncthreads();

    const int nIter = K / BKK;
    int buf = 0;

    for (int it = 0; it < nIter; it++) {
        // prefetch next tile into registers
        const bool hasNext = (it + 1 < nIter);
        if (hasNext) {
            const int k0 = (it + 1) * BKK;
            ra = *(const float4*)(Aptr + k0);
            const int kg = k0 + bk;
            const float* row = (kg < Ksplit) ? (B0 + (size_t)kg * NPTS)
                                             : (B1 + (size_t)(kg - Ksplit) * NPTS);
            rb = *(const float4*)(row + nBase + bn);
        }

        // compute current buffer
        #pragma unroll
        for (int k = 0; k < BKK; k++) {
            float a[8], bb[8];
            *(float4*)&a[0]  = *(const float4*)&sA[buf][k][ty * 4];
            *(float4*)&a[4]  = *(const float4*)&sA[buf][k][64 + ty * 4];
            *(float4*)&bb[0] = *(const float4*)&sB[buf][k][tx * 4];
            *(float4*)&bb[4] = *(const float4*)&sB[buf][k][64 + tx * 4];
            #pragma unroll
            for (int i = 0; i < 8; i++)
                #pragma unroll
                for (int jj = 0; jj < 8; jj++)
                    acc[i][jj] = fmaf(a[i], bb[jj], acc[i][jj]);
        }

        // store next tile to the other buffer
        if (hasNext) {
            buf ^= 1;
            sA[buf][ak + 0][am] = ra.x;
            sA[buf][ak + 1][am] = ra.y;
            sA[buf][ak + 2][am] = ra.z;
            sA[buf][ak + 3][am] = ra.w;
            *(float4*)&sB[buf][bk][bn] = rb;
            __syncthreads();
        }
    }

    // ---- epilogue: bias + relu + store ----
    #pragma unroll
    for (int i = 0; i < 8; i++) {
        const int m = mBase + ((i < 4) ? (ty * 4 + i) : (64 + ty * 4 + (i - 4)));
        const float bv = bias[m];
        float4 r0, r1;
        r0.x = fmaxf(acc[i][0] + bv, 0.0f);
        r0.y = fmaxf(acc[i][1] + bv, 0.0f);
        r0.z = fmaxf(acc[i][2] + bv, 0.0f);
        r0.w = fmaxf(acc[i][3] + bv, 0.0f);
        r1.x = fmaxf(acc[i][4] + bv, 0.0f);
        r1.y = fmaxf(acc[i][5] + bv, 0.0f);
        r1.z = fmaxf(acc[i][6] + bv, 0.0f);
        r1.w = fmaxf(acc[i][7] + bv, 0.0f);
        float* crow = Cout + (size_t)m * NPTS + nBase;
        *(float4*)&crow[tx * 4]      = r0;
        *(float4*)&crow[64 + tx * 4] = r1;
    }
}

// ---------------- launch -----------------------------------------------------
extern "C" void kernel_launch(void* const* d_in, const int* in_sizes, int n_in,
                              void* d_out, int out_size)
{
    const float* unknown = (const float*)d_in[0];
    const float* known   = (const float*)d_in[1];
    const float* uf      = (const float*)d_in[2];
    const float* kf      = (const float*)d_in[3];
    const float* W1      = (const float*)d_in[4];
    const float* b1      = (const float*)d_in[5];
    const float* W2      = (const float*)d_in[6];
    const float* b2      = (const float*)d_in[7];
    float* out = (float*)d_out;

    float* p_Xi = nullptr;
    float* p_Y1 = nullptr;
    cudaGetSymbolAddress((void**)&p_Xi, g_Xi);
    cudaGetSymbolAddress((void**)&p_Y1, g_Y1);

    three_nn_kernel<<<dim3(NPTS / 256, BATCH), 256>>>(unknown, known);
    interp_kernel  <<<dim3(NPTS / 32,  BATCH), 256>>>(kf);

    // layer 1: K = 384 (256 from g_Xi, 128 directly from unknown_feats)
    gemm_bias_relu<<<dim3(NPTS / BN, CMID / BM, BATCH), 256>>>(
        W1, b1,
        p_Xi, (unsigned long long)C2 * NPTS,
        uf,   (unsigned long long)C1 * NPTS,
        p_Y1, (unsigned long long)CMID * NPTS,
        KDIM, C2);

    // layer 2: K = 256, single source
    gemm_bias_relu<<<dim3(NPTS / BN, C2 / BM, BATCH), 256>>>(
        W2, b2,
        p_Y1, (unsigned long long)CMID * NPTS,
        p_Y1, (unsigned long long)CMID * NPTS,
        out,  (unsigned long long)C2 * NPTS,
        CMID, CMID);
}

// round 4
// speedup vs baseline: 1.4881x; 1.2958x over previous
#include <cuda_runtime.h>
#include <cuda_bf16.h>
#include <math.h>
#include <stdint.h>

#define BATCH 8
#define NPTS  8192
#define MPTS  2048
#define C1    128
#define C2    256
#define CMID  256

// ---------------- scratch (device globals; no allocation allowed) ----------
__device__ int   g_idx[BATCH * NPTS * 3];
__device__ float g_w  [BATCH * NPTS * 3];
__device__ __align__(256) float g_Xi [BATCH * C2   * NPTS];          // fp32 [b][c][n]
__device__ __align__(256) float g_Y1 [BATCH * CMID * NPTS];          // fp32 [b][m][n]
__device__ __align__(256) __nv_bfloat16 g_B1 [BATCH * NPTS * 768];   // [b][n][hi384|lo384]
__device__ __align__(256) __nv_bfloat16 g_B2 [BATCH * NPTS * 512];   // [b][n][hi256|lo256]
__device__ __align__(256) __nv_bfloat16 g_W1s[256 * 1152];           // [m][Whi|Whi|Wlo]
__device__ __align__(256) __nv_bfloat16 g_W2s[256 * 768];

// ---------------- helpers ----------------------------------------------------
__device__ __forceinline__ uint32_t smem_u32(const void* p) {
    uint32_t a;
    asm("{ .reg .u64 t; cvta.to.shared.u64 t, %1; cvt.u32.u64 %0, t; }" : "=r"(a) : "l"(p));
    return a;
}
#define CP_ASYNC16(dst, src) \
    asm volatile("cp.async.cg.shared.global [%0], [%1], 16;" :: "r"(dst), "l"(src))
#define CP_COMMIT() asm volatile("cp.async.commit_group;" ::: "memory")
#define CP_WAIT0()  asm volatile("cp.async.wait_group 0;" ::: "memory")
#define CP_WAIT1()  asm volatile("cp.async.wait_group 1;" ::: "memory")

#define LDSM4(r0, r1, r2, r3, addr) \
    asm volatile("ldmatrix.sync.aligned.m8n8.x4.shared.b16 {%0,%1,%2,%3}, [%4];" \
        : "=r"(r0), "=r"(r1), "=r"(r2), "=r"(r3) : "r"(addr))

#define MMA16816(d, a, b) \
    asm volatile("mma.sync.aligned.m16n8k16.row.col.f32.bf16.bf16.f32 " \
        "{%0,%1,%2,%3}, {%4,%5,%6,%7}, {%8,%9}, {%0,%1,%2,%3};" \
        : "+f"(d[0]), "+f"(d[1]), "+f"(d[2]), "+f"(d[3]) \
        : "r"(a[0]), "r"(a[1]), "r"(a[2]), "r"(a[3]), "r"(b[0]), "r"(b[1]))

// ---------------- kernel 1: three_nn + weights ------------------------------
__global__ __launch_bounds__(256)
void three_nn_kernel(const float* __restrict__ unknown,
                     const float* __restrict__ known)
{
    __shared__ float4 sk[MPTS];
    const int b = blockIdx.y;
    const int j = blockIdx.x * blockDim.x + threadIdx.x;

    const float* kb = known + (size_t)b * MPTS * 3;
    for (int i = threadIdx.x; i < MPTS; i += blockDim.x) {
        float x = kb[i * 3 + 0], y = kb[i * 3 + 1], z = kb[i * 3 + 2];
        sk[i] = make_float4(x, y, z, x * x + y * y + z * z);
    }
    __syncthreads();

    const float* up = unknown + ((size_t)b * NPTS + j) * 3;
    const float ux = up[0], uy = up[1], uz = up[2];
    const float u2 = ux * ux + uy * uy + uz * uz;

    float d0 = 3.4e38f, d1 = 3.4e38f, d2v = 3.4e38f;
    int i0 = 0, i1 = 0, i2 = 0;

    #pragma unroll 4
    for (int i = 0; i < MPTS; i++) {
        float4 k = sk[i];
        float dot = ux * k.x + uy * k.y + uz * k.z;
        float d = u2 + k.w - 2.0f * dot;
        if (d < d0)       { d2v = d1; i2 = i1; d1 = d0; i1 = i0; d0 = d; i0 = i; }
        else if (d < d1)  { d2v = d1; i2 = i1; d1 = d;  i1 = i; }
        else if (d < d2v) { d2v = d;  i2 = i; }
    }

    float s0 = sqrtf(fmaxf(d0, 0.0f));
    float s1 = sqrtf(fmaxf(d1, 0.0f));
    float s2 = sqrtf(fmaxf(d2v, 0.0f));
    float r0 = 1.0f / (s0 + 1e-8f);
    float r1 = 1.0f / (s1 + 1e-8f);
    float r2 = 1.0f / (s2 + 1e-8f);
    float rs = r0 + r1 + r2;

    const int o = ((b * NPTS) + j) * 3;
    g_idx[o + 0] = i0; g_idx[o + 1] = i1; g_idx[o + 2] = i2;
    g_w[o + 0] = r0 / rs; g_w[o + 1] = r1 / rs; g_w[o + 2] = r2 / rs;
}

// ---------------- kernel 2: three_interpolate -> g_Xi (fp32 [c][n]) ---------
__global__ __launch_bounds__(256)
void interp_kernel(const float* __restrict__ kf)
{
    const int b    = blockIdx.y;
    const int lane = threadIdx.x & 31;
    const int warp = threadIdx.x >> 5;
    const int j    = blockIdx.x * 32 + lane;

    const int o = ((b * NPTS) + j) * 3;
    const int   i0 = g_idx[o + 0], i1 = g_idx[o + 1], i2 = g_idx[o + 2];
    const float w0 = g_w[o + 0],   w1 = g_w[o + 1],   w2 = g_w[o + 2];

    const float* kfb = kf   + (size_t)b * C2 * MPTS;
    float*       xb  = g_Xi + (size_t)b * C2 * NPTS;

    for (int c = warp; c < C2; c += 8) {
        const float* row = kfb + (size_t)c * MPTS;
        xb[(size_t)c * NPTS + j] = row[i0] * w0 + row[i1] * w1 + row[i2] * w2;
    }
}

// ---------------- weight split: W[256][K] -> Ws[256][hi K|hi K|lo K] --------
__global__ __launch_bounds__(256)
void convert_w_kernel(const float* __restrict__ W, __nv_bfloat16* __restrict__ Ws, int K)
{
    int idx = blockIdx.x * 256 + threadIdx.x;
    if (idx >= 256 * K) return;
    int m = idx / K, k = idx - m * K;
    float w = W[idx];
    __nv_bfloat16 hi = __float2bfloat16(w);
    __nv_bfloat16 lo = __float2bfloat16(w - __bfloat162float(hi));
    __nv_bfloat16* row = Ws + (size_t)m * 3 * K;
    row[k] = hi; row[K + k] = hi; row[2 * K + k] = lo;
}

// ---------------- transpose + bf16 hi/lo split ------------------------------
__global__ __launch_bounds__(256)
void transpose_convert_kernel(const float* __restrict__ src0, int rows0,
                              const float* __restrict__ src1, int rows1,
                              __nv_bfloat16* __restrict__ dst, int Ktot)
{
    extern __shared__ float s[];              // [Ktot][33]
    const int b    = blockIdx.y;
    const int j0   = blockIdx.x * 32;
    const int tid  = threadIdx.x;
    const int lane = tid & 31;
    const int warp = tid >> 5;

    for (int c = warp; c < Ktot; c += 8) {
        const float* sp = (c < rows0)
            ? src0 + ((size_t)b * rows0 + c) * NPTS
            : src1 + ((size_t)b * rows1 + (c - rows0)) * NPTS;
        s[c * 33 + lane] = sp[j0 + lane];
    }
    __syncthreads();

    const int qn = Ktot >> 6;
    for (int t = 0; t < 4; t++) {
        int j = warp * 4 + t;
        __nv_bfloat16* row = dst + ((size_t)b * NPTS + j0 + j) * 2 * Ktot;
        for (int q = 0; q < qn; q++) {
            int c = q * 64 + lane * 2;
            float v0 = s[c * 33 + j];
            float v1 = s[(c + 1) * 33 + j];
            __nv_bfloat16 h0 = __float2bfloat16(v0);
            __nv_bfloat16 h1 = __float2bfloat16(v1);
            __nv_bfloat16 l0 = __float2bfloat16(v0 - __bfloat162float(h0));
            __nv_bfloat16 l1 = __float2bfloat16(v1 - __bfloat162float(h1));
            uint32_t hp = ((uint32_t)__bfloat16_as_ushort(h1) << 16) | __bfloat16_as_ushort(h0);
            uint32_t lp = ((uint32_t)__bfloat16_as_ushort(l1) << 16) | __bfloat16_as_ushort(l0);
            *(uint32_t*)(row + c)        = hp;
            *(uint32_t*)(row + Ktot + c) = lp;
        }
    }
}

// ---------------- mma.sync GEMM: C[m,n] = relu(Ws . B^T + bias) -------------
// A = Ws [256][3*Ksrc] bf16 row-major; B = [b][n][2*Ksrc] bf16 (hi|lo)
// K' = 3*Ksrc, chunk schedule: hi, lo, hi  (Whi.Xhi + Whi.Xlo + Wlo.Xhi)
// CTA tile 128x128x32, 8 warps, warp tile 64x32, m16n8k16 mma, cp.async x2 buf
#define PITCH 80                 // smem row pitch bytes (40 bf16)
#define ATILE 10240              // 128*80
#define STAGE 20480              // A + B per stage

__global__ __launch_bounds__(256)
void gemm_mma_kernel(const __nv_bfloat16* __restrict__ Ws,
                     const float* __restrict__ bias,
                     const __nv_bfloat16* __restrict__ Bmat,
                     float* __restrict__ Cout,
                     int Ksrc)
{
    __shared__ __align__(16) char smem[2 * STAGE];
    const uint32_t sb = smem_u32(smem);

    const int tid  = threadIdx.x;
    const int wid  = tid >> 5;
    const int lane = tid & 31;
    const int wr   = wid >> 2;          // 0..1  (m half)
    const int wc   = wid & 3;           // 0..3  (n quarter)

    const int K3        = 3 * Ksrc;
    const int kseg      = Ksrc >> 5;    // Ksrc/32
    const int nChunks   = 3 * kseg;
    const int strideRow = 2 * Ksrc;

    const int b     = blockIdx.z;
    const int mBase = blockIdx.y * 128;
    const int nBase = blockIdx.x * 128;

    const __nv_bfloat16* Asrc = Ws + (size_t)mBase * K3;
    const __nv_bfloat16* Bsrc = Bmat + ((size_t)b * NPTS + nBase) * strideRow;
    float* Cb = Cout + (size_t)b * 256 * NPTS;

    // per-thread load map: 512 chunks of 16B per operand, 2 per thread
    const int r0l = tid >> 2;                 // 0..63
    const int c0l = tid & 3;                  // 0..3

    float acc[4][4][4];
    #pragma unroll
    for (int i = 0; i < 4; i++)
        #pragma unroll
        for (int j = 0; j < 4; j++)
            #pragma unroll
            for (int q = 0; q < 4; q++) acc[i][j][q] = 0.0f;

    // ---- stage loader (inline) ----
    #define LOAD_STAGE(sidx, buf) do {                                          \
        int _s = (sidx);                                                        \
        int _srcOff;                                                            \
        if      (_s < kseg)     _srcOff = _s * 32;                              \
        else if (_s < 2 * kseg) _srcOff = Ksrc + (_s - kseg) * 32;              \
        else                    _srcOff = (_s - 2 * kseg) * 32;                 \
        uint32_t _ab = sb + (buf) * STAGE;                                      \
        uint32_t _bb = _ab + ATILE;                                             \
        _Pragma("unroll")                                                       \
        for (int _t = 0; _t < 2; _t++) {                                        \
            int _row = r0l + _t * 64;                                           \
            CP_ASYNC16(_ab + _row * PITCH + c0l * 16,                           \
                       Asrc + (size_t)_row * K3 + _s * 32 + c0l * 8);           \
            CP_ASYNC16(_bb + _row * PITCH + c0l * 16,                           \
                       Bsrc + (size_t)_row * strideRow + _srcOff + c0l * 8);    \
        }                                                                       \
    } while (0)

    LOAD_STAGE(0, 0);
    CP_COMMIT();

    for (int s = 0; s < nChunks; s++) {
        const int buf = s & 1;
        if (s + 1 < nChunks) {
            LOAD_STAGE(s + 1, buf ^ 1);
            CP_COMMIT();
            CP_WAIT1();
        } else {
            CP_WAIT0();
        }
        __syncthreads();

        const uint32_t aB = sb + buf * STAGE;
        const uint32_t bB = aB + ATILE;

        #pragma unroll
        for (int kk = 0; kk < 2; kk++) {
            uint32_t af[4][4];
            uint32_t bf[4][4];   // [npair][4]
            #pragma unroll
            for (int i = 0; i < 4; i++) {
                int row = wr * 64 + i * 16 + (lane & 15);
                uint32_t addr = aB + row * PITCH + kk * 32 + (lane >> 4) * 16;
                LDSM4(af[i][0], af[i][1], af[i][2], af[i][3], addr);
            }
            #pragma unroll
            for (int jp = 0; jp < 2; jp++) {
                int row = wc * 32 + jp * 16 + (lane & 15);
                uint32_t addr = bB + row * PITCH + kk * 32 + (lane >> 4) * 16;
                LDSM4(bf[jp][0], bf[jp][1], bf[jp][2], bf[jp][3], addr);
            }
            #pragma unroll
            for (int i = 0; i < 4; i++) {
                #pragma unroll
                for (int jp = 0; jp < 2; jp++) {
                    uint32_t b0[2] = { bf[jp][0], bf[jp][2] };   // n tile jp*2
                    uint32_t b1[2] = { bf[jp][1], bf[jp][3] };   // n tile jp*2+1
                    MMA16816(acc[i][jp * 2 + 0], af[i], b0);
                    MMA16816(acc[i][jp * 2 + 1], af[i], b1);
                }
            }
        }
        __syncthreads();
    }

    // ---- epilogue: bias + relu + store fp32 ----
    #pragma unroll
    for (int i = 0; i < 4; i++) {
        const int r0 = mBase + wr * 64 + i * 16 + (lane >> 2);
        const float bv0 = bias[r0];
        const float bv1 = bias[r0 + 8];
        float* cr0 = Cb + (size_t)r0 * NPTS;
        float* cr1 = Cb + (size_t)(r0 + 8) * NPTS;
        #pragma unroll
        for (int jn = 0; jn < 4; jn++) {
            const int col = nBase + wc * 32 + jn * 8 + (lane & 3) * 2;
            float2 v0, v1;
            v0.x = fmaxf(acc[i][jn][0] + bv0, 0.0f);
            v0.y = fmaxf(acc[i][jn][1] + bv0, 0.0f);
            v1.x = fmaxf(acc[i][jn][2] + bv1, 0.0f);
            v1.y = fmaxf(acc[i][jn][3] + bv1, 0.0f);
            *(float2*)&cr0[col] = v0;
            *(float2*)&cr1[col] = v1;
        }
    }
}

// ---------------- launch -----------------------------------------------------
extern "C" void kernel_launch(void* const* d_in, const int* in_sizes, int n_in,
                              void* d_out, int out_size)
{
    const float* unknown = (const float*)d_in[0];
    const float* known   = (const float*)d_in[1];
    const float* uf      = (const float*)d_in[2];
    const float* kf      = (const float*)d_in[3];
    const float* W1      = (const float*)d_in[4];
    const float* b1      = (const float*)d_in[5];
    const float* W2      = (const float*)d_in[6];
    const float* b2      = (const float*)d_in[7];
    float* out = (float*)d_out;

    float *p_Xi = nullptr, *p_Y1 = nullptr;
    __nv_bfloat16 *p_B1 = nullptr, *p_B2 = nullptr, *p_W1s = nullptr, *p_W2s = nullptr;
    cudaGetSymbolAddress((void**)&p_Xi,  g_Xi);
    cudaGetSymbolAddress((void**)&p_Y1,  g_Y1);
    cudaGetSymbolAddress((void**)&p_B1,  g_B1);
    cudaGetSymbolAddress((void**)&p_B2,  g_B2);
    cudaGetSymbolAddress((void**)&p_W1s, g_W1s);
    cudaGetSymbolAddress((void**)&p_W2s, g_W2s);

    cudaFuncSetAttribute(transpose_convert_kernel,
                         cudaFuncAttributeMaxDynamicSharedMemorySize, 384 * 33 * 4);

    three_nn_kernel<<<dim3(NPTS / 256, BATCH), 256>>>(unknown, known);
    interp_kernel  <<<dim3(NPTS / 32,  BATCH), 256>>>(kf);

    convert_w_kernel<<<(256 * 384 + 255) / 256, 256>>>(W1, p_W1s, 384);
    convert_w_kernel<<<(256 * 256 + 255) / 256, 256>>>(W2, p_W2s, 256);

    // B1: [Xi(256) ; uf(128)] -> [n][hi384|lo384]
    transpose_convert_kernel<<<dim3(NPTS / 32, BATCH), 256, 384 * 33 * 4>>>(
        p_Xi, 256, uf, 128, p_B1, 384);

    // layer 1: K'=1152 -> Y1 fp32 [m][n]
    gemm_mma_kernel<<<dim3(NPTS / 128, 2, BATCH), 256>>>(
        p_W1s, b1, p_B1, p_Y1, 384);

    // B2: Y1 -> [n][hi256|lo256]
    transpose_convert_kernel<<<dim3(NPTS / 32, BATCH), 256, 256 * 33 * 4>>>(
        p_Y1, 256, p_Y1, 0, p_B2, 256);

    // layer 2: K'=768 -> out fp32 [m][n]
    gemm_mma_kernel<<<dim3(NPTS / 128, 2, BATCH), 256>>>(
        p_W2s, b2, p_B2, out, 256);
}

// round 5
// speedup vs baseline: 2.0265x; 1.3618x over previous
#include <cuda_runtime.h>
#include <cuda_bf16.h>
#include <math.h>
#include <stdint.h>

#define BATCH 8
#define NPTS  8192
#define MPTS  2048
#define C1    128
#define C2    256
#define CMID  256

// ---------------- scratch (device globals; no allocation allowed) ----------
__device__ int   g_idx[BATCH * NPTS * 3];
__device__ float g_w  [BATCH * NPTS * 3];
__device__ __align__(256) float g_kfT[BATCH * MPTS * C2];            // kf transposed [b][m][c]
__device__ __align__(256) __nv_bfloat16 g_B1 [BATCH * NPTS * 768];   // [b][n][hi384|lo384]
__device__ __align__(256) __nv_bfloat16 g_B2 [BATCH * NPTS * 512];   // [b][n][hi256|lo256]
__device__ __align__(256) __nv_bfloat16 g_W1s[256 * 1152];           // [m][Whi|Whi|Wlo]
__device__ __align__(256) __nv_bfloat16 g_W2s[256 * 768];

// ---------------- helpers ----------------------------------------------------
__device__ __forceinline__ uint32_t smem_u32(const void* p) {
    uint32_t a;
    asm("{ .reg .u64 t; cvta.to.shared.u64 t, %1; cvt.u32.u64 %0, t; }" : "=r"(a) : "l"(p));
    return a;
}
#define CP_ASYNC16(dst, src) \
    asm volatile("cp.async.cg.shared.global [%0], [%1], 16;" :: "r"(dst), "l"(src))
#define CP_COMMIT() asm volatile("cp.async.commit_group;" ::: "memory")
#define CP_WAIT0()  asm volatile("cp.async.wait_group 0;" ::: "memory")
#define CP_WAIT1()  asm volatile("cp.async.wait_group 1;" ::: "memory")

#define LDSM4(r0, r1, r2, r3, addr) \
    asm volatile("ldmatrix.sync.aligned.m8n8.x4.shared.b16 {%0,%1,%2,%3}, [%4];" \
        : "=r"(r0), "=r"(r1), "=r"(r2), "=r"(r3) : "r"(addr))

#define MMA16816(d, a, b) \
    asm volatile("mma.sync.aligned.m16n8k16.row.col.f32.bf16.bf16.f32 " \
        "{%0,%1,%2,%3}, {%4,%5,%6,%7}, {%8,%9}, {%0,%1,%2,%3};" \
        : "+f"(d[0]), "+f"(d[1]), "+f"(d[2]), "+f"(d[3]) \
        : "r"(a[0]), "r"(a[1]), "r"(a[2]), "r"(a[3]), "r"(b[0]), "r"(b[1]))

__device__ __forceinline__ uint32_t pack_bf16(float a, float b) {
    __nv_bfloat16 x = __float2bfloat16(a);
    __nv_bfloat16 y = __float2bfloat16(b);
    return ((uint32_t)__bfloat16_as_ushort(y) << 16) | __bfloat16_as_ushort(x);
}

// ---------------- kernel 1: three_nn + weights ------------------------------
__global__ __launch_bounds__(256)
void three_nn_kernel(const float* __restrict__ unknown,
                     const float* __restrict__ known)
{
    __shared__ float4 sk[MPTS];
    const int b = blockIdx.y;
    const int j = blockIdx.x * blockDim.x + threadIdx.x;

    const float* kb = known + (size_t)b * MPTS * 3;
    for (int i = threadIdx.x; i < MPTS; i += blockDim.x) {
        float x = kb[i * 3 + 0], y = kb[i * 3 + 1], z = kb[i * 3 + 2];
        sk[i] = make_float4(x, y, z, x * x + y * y + z * z);
    }
    __syncthreads();

    const float* up = unknown + ((size_t)b * NPTS + j) * 3;
    const float ux = up[0], uy = up[1], uz = up[2];
    const float u2 = ux * ux + uy * uy + uz * uz;

    float d0 = 3.4e38f, d1 = 3.4e38f, d2v = 3.4e38f;
    int i0 = 0, i1 = 0, i2 = 0;

    #pragma unroll 4
    for (int i = 0; i < MPTS; i++) {
        float4 k = sk[i];
        float dot = ux * k.x + uy * k.y + uz * k.z;
        float d = u2 + k.w - 2.0f * dot;
        if (d < d0)       { d2v = d1; i2 = i1; d1 = d0; i1 = i0; d0 = d; i0 = i; }
        else if (d < d1)  { d2v = d1; i2 = i1; d1 = d;  i1 = i; }
        else if (d < d2v) { d2v = d;  i2 = i; }
    }

    float s0 = sqrtf(fmaxf(d0, 0.0f));
    float s1 = sqrtf(fmaxf(d1, 0.0f));
    float s2 = sqrtf(fmaxf(d2v, 0.0f));
    float r0 = 1.0f / (s0 + 1e-8f);
    float r1 = 1.0f / (s1 + 1e-8f);
    float r2 = 1.0f / (s2 + 1e-8f);
    float rs = r0 + r1 + r2;

    const int o = ((b * NPTS) + j) * 3;
    g_idx[o + 0] = i0; g_idx[o + 1] = i1; g_idx[o + 2] = i2;
    g_w[o + 0] = r0 / rs; g_w[o + 1] = r1 / rs; g_w[o + 2] = r2 / rs;
}

// ---------------- kernel 2: transpose kf -> kfT [b][m][c] -------------------
__global__ __launch_bounds__(256)
void kf_transpose_kernel(const float* __restrict__ kf, float* __restrict__ kfT)
{
    __shared__ float s[32][33];
    const int b  = blockIdx.z;
    const int m0 = blockIdx.x * 32;
    const int c0 = blockIdx.y * 32;
    const int lane = threadIdx.x & 31, r = threadIdx.x >> 5;

    #pragma unroll
    for (int k = 0; k < 4; k++) {
        int c = r + k * 8;
        s[c][lane] = kf[((size_t)b * C2 + c0 + c) * MPTS + m0 + lane];
    }
    __syncthreads();
    #pragma unroll
    for (int k = 0; k < 4; k++) {
        int m = r + k * 8;
        kfT[((size_t)b * MPTS + m0 + m) * C2 + c0 + lane] = s[lane][m];
    }
}

// ---------------- kernel 3: fused interp + hi/lo convert -> B1[0..255] ------
// warp per point: 3 coalesced 1KB row reads from kfT, weighted sum, split.
__global__ __launch_bounds__(256)
void interp_fused_kernel(const float* __restrict__ kfT, __nv_bfloat16* __restrict__ B1)
{
    const int b    = blockIdx.y;
    const int lane = threadIdx.x & 31;
    const int warp = threadIdx.x >> 5;
    const int jbase = blockIdx.x * 32 + warp * 4;

    #pragma unroll
    for (int t = 0; t < 4; t++) {
        const int j = jbase + t;
        const int o = ((b * NPTS) + j) * 3;
        const int   i0 = g_idx[o + 0], i1 = g_idx[o + 1], i2 = g_idx[o + 2];
        const float w0 = g_w[o + 0],   w1 = g_w[o + 1],   w2 = g_w[o + 2];

        const float* r0 = kfT + ((size_t)b * MPTS + i0) * C2 + lane * 8;
        const float* r1 = kfT + ((size_t)b * MPTS + i1) * C2 + lane * 8;
        const float* r2 = kfT + ((size_t)b * MPTS + i2) * C2 + lane * 8;

        float4 a0 = *(const float4*)(r0);
        float4 a1 = *(const float4*)(r0 + 4);
        float4 b0 = *(const float4*)(r1);
        float4 b1 = *(const float4*)(r1 + 4);
        float4 c0 = *(const float4*)(r2);
        float4 c1 = *(const float4*)(r2 + 4);

        float v[8];
        v[0] = a0.x * w0 + b0.x * w1 + c0.x * w2;
        v[1] = a0.y * w0 + b0.y * w1 + c0.y * w2;
        v[2] = a0.z * w0 + b0.z * w1 + c0.z * w2;
        v[3] = a0.w * w0 + b0.w * w1 + c0.w * w2;
        v[4] = a1.x * w0 + b1.x * w1 + c1.x * w2;
        v[5] = a1.y * w0 + b1.y * w1 + c1.y * w2;
        v[6] = a1.z * w0 + b1.z * w1 + c1.z * w2;
        v[7] = a1.w * w0 + b1.w * w1 + c1.w * w2;

        uint4 hi, lo;
        float l[8];
        #pragma unroll
        for (int q = 0; q < 8; q++)
            l[q] = v[q] - __bfloat162float(__float2bfloat16(v[q]));
        hi.x = pack_bf16(v[0], v[1]); hi.y = pack_bf16(v[2], v[3]);
        hi.z = pack_bf16(v[4], v[5]); hi.w = pack_bf16(v[6], v[7]);
        lo.x = pack_bf16(l[0], l[1]); lo.y = pack_bf16(l[2], l[3]);
        lo.z = pack_bf16(l[4], l[5]); lo.w = pack_bf16(l[6], l[7]);

        __nv_bfloat16* row = B1 + ((size_t)b * NPTS + j) * 768;
        *(uint4*)(row + lane * 8)       = hi;
        *(uint4*)(row + 384 + lane * 8) = lo;
    }
}

// ---------------- kernel 4: uf -> B1[256..383] slices ------------------------
__global__ __launch_bounds__(256)
void uf_to_B1_kernel(const float* __restrict__ uf, __nv_bfloat16* __restrict__ B1)
{
    __shared__ float s[C1][33];
    const int b    = blockIdx.y;
    const int j0   = blockIdx.x * 32;
    const int lane = threadIdx.x & 31;
    const int warp = threadIdx.x >> 5;

    #pragma unroll
    for (int k = 0; k < 16; k++) {
        int c = warp + k * 8;
        s[c][lane] = uf[((size_t)b * C1 + c) * NPTS + j0 + lane];
    }
    __syncthreads();

    #pragma unroll
    for (int t = 0; t < 4; t++) {
        int jl = warp * 4 + t;
        __nv_bfloat16* row = B1 + ((size_t)b * NPTS + j0 + jl) * 768;
        #pragma unroll
        for (int q = 0; q < 2; q++) {
            int c = q * 64 + lane * 2;
            float v0 = s[c][jl], v1 = s[c + 1][jl];
            float l0 = v0 - __bfloat162float(__float2bfloat16(v0));
            float l1 = v1 - __bfloat162float(__float2bfloat16(v1));
            *(uint32_t*)(row + 256 + c) = pack_bf16(v0, v1);
            *(uint32_t*)(row + 640 + c) = pack_bf16(l0, l1);
        }
    }
}

// ---------------- weight split: W[256][K] -> Ws[256][hi K|hi K|lo K] --------
__global__ __launch_bounds__(256)
void convert_w_kernel(const float* __restrict__ W, __nv_bfloat16* __restrict__ Ws, int K)
{
    int idx = blockIdx.x * 256 + threadIdx.x;
    if (idx >= 256 * K) return;
    int m = idx / K, k = idx - m * K;
    float w = W[idx];
    __nv_bfloat16 hi = __float2bfloat16(w);
    __nv_bfloat16 lo = __float2bfloat16(w - __bfloat162float(hi));
    __nv_bfloat16* row = Ws + (size_t)m * 3 * K;
    row[k] = hi; row[K + k] = hi; row[2 * K + k] = lo;
}

// ---------------- mma.sync GEMM + fused epilogue -----------------------------
// A = Ws [256][3*Ksrc]; B = [b][n][2*Ksrc] (hi|lo). K' = 3*Ksrc (hi,lo,hi).
// CTA 128x128x32, 8 warps, m16n8k16, cp.async double buffer.
// Epilogue: B2out != null -> write transposed bf16 hi/lo via smem staging;
//           else fp32 rows of Cout.
#define PITCH 80
#define ATILE 10240
#define STAGE 20480

__global__ __launch_bounds__(256)
void gemm_mma_kernel(const __nv_bfloat16* __restrict__ Ws,
                     const float* __restrict__ bias,
                     const __nv_bfloat16* __restrict__ Bmat,
                     float* __restrict__ Cout,
                     __nv_bfloat16* __restrict__ B2out,
                     int Ksrc)
{
    __shared__ __align__(16) char smem[2 * STAGE];
    const uint32_t sb = smem_u32(smem);

    const int tid  = threadIdx.x;
    const int wid  = tid >> 5;
    const int lane = tid & 31;
    const int wr   = wid >> 2;
    const int wc   = wid & 3;

    const int K3        = 3 * Ksrc;
    const int kseg      = Ksrc >> 5;
    const int nChunks   = 3 * kseg;
    const int strideRow = 2 * Ksrc;

    const int b     = blockIdx.z;
    const int mBase = blockIdx.y * 128;
    const int nBase = blockIdx.x * 128;

    const __nv_bfloat16* Asrc = Ws + (size_t)mBase * K3;
    const __nv_bfloat16* Bsrc = Bmat + ((size_t)b * NPTS + nBase) * strideRow;

    const int r0l = tid >> 2;
    const int c0l = tid & 3;

    float acc[4][4][4];
    #pragma unroll
    for (int i = 0; i < 4; i++)
        #pragma unroll
        for (int j = 0; j < 4; j++)
            #pragma unroll
            for (int q = 0; q < 4; q++) acc[i][j][q] = 0.0f;

    #define LOAD_STAGE(sidx, buf) do {                                          \
        int _s = (sidx);                                                        \
        int _srcOff;                                                            \
        if      (_s < kseg)     _srcOff = _s * 32;                              \
        else if (_s < 2 * kseg) _srcOff = Ksrc + (_s - kseg) * 32;              \
        else                    _srcOff = (_s - 2 * kseg) * 32;                 \
        uint32_t _ab = sb + (buf) * STAGE;                                      \
        uint32_t _bb = _ab + ATILE;                                             \
        _Pragma("unroll")                                                       \
        for (int _t = 0; _t < 2; _t++) {                                        \
            int _row = r0l + _t * 64;                                           \
            CP_ASYNC16(_ab + _row * PITCH + c0l * 16,                           \
                       Asrc + (size_t)_row * K3 + _s * 32 + c0l * 8);           \
            CP_ASYNC16(_bb + _row * PITCH + c0l * 16,                           \
                       Bsrc + (size_t)_row * strideRow + _srcOff + c0l * 8);    \
        }                                                                       \
    } while (0)

    LOAD_STAGE(0, 0);
    CP_COMMIT();

    for (int s = 0; s < nChunks; s++) {
        const int buf = s & 1;
        if (s + 1 < nChunks) {
            LOAD_STAGE(s + 1, buf ^ 1);
            CP_COMMIT();
            CP_WAIT1();
        } else {
            CP_WAIT0();
        }
        __syncthreads();

        const uint32_t aB = sb + buf * STAGE;
        const uint32_t bB = aB + ATILE;

        #pragma unroll
        for (int kk = 0; kk < 2; kk++) {
            uint32_t af[4][4];
            uint32_t bf[2][4];
            #pragma unroll
            for (int i = 0; i < 4; i++) {
                int row = wr * 64 + i * 16 + (lane & 15);
                uint32_t addr = aB + row * PITCH + kk * 32 + (lane >> 4) * 16;
                LDSM4(af[i][0], af[i][1], af[i][2], af[i][3], addr);
            }
            #pragma unroll
            for (int jp = 0; jp < 2; jp++) {
                int row = wc * 32 + jp * 16 + (lane & 15);
                uint32_t addr = bB + row * PITCH + kk * 32 + (lane >> 4) * 16;
                LDSM4(bf[jp][0], bf[jp][1], bf[jp][2], bf[jp][3], addr);
            }
            #pragma unroll
            for (int i = 0; i < 4; i++) {
                #pragma unroll
                for (int jp = 0; jp < 2; jp++) {
                    uint32_t b0[2] = { bf[jp][0], bf[jp][2] };
                    uint32_t b1[2] = { bf[jp][1], bf[jp][3] };
                    MMA16816(acc[i][jp * 2 + 0], af[i], b0);
                    MMA16816(acc[i][jp * 2 + 1], af[i], b1);
                }
            }
        }
        __syncthreads();
    }

    if (B2out) {
        // staged transpose to B2 [n][hi256|lo256], planes: 0=hi, 1=lo
        __nv_bfloat16* sm = (__nv_bfloat16*)smem;        // [128][136]
        #pragma unroll 1
        for (int plane = 0; plane < 2; plane++) {
            __syncthreads();
            #pragma unroll
            for (int i = 0; i < 4; i++) {
                const int ml0 = wr * 64 + i * 16 + (lane >> 2);
                const float bv0 = bias[mBase + ml0];
                const float bv1 = bias[mBase + ml0 + 8];
                #pragma unroll
                for (int jn = 0; jn < 4; jn++) {
                    const int nl = wc * 32 + jn * 8 + (lane & 3) * 2;
                    #pragma unroll
                    for (int q = 0; q < 4; q++) {
                        const int ml = ml0 + ((q >= 2) ? 8 : 0);
                        const int nn = nl + (q & 1);
                        const float v = fmaxf(acc[i][jn][q] + ((q >= 2) ? bv1 : bv0), 0.0f);
                        __nv_bfloat16 h = __float2bfloat16(v);
                        __nv_bfloat16 val = (plane == 0)
                            ? h : __float2bfloat16(v - __bfloat162float(h));
                        sm[nn * 136 + ml] = val;
                    }
                }
            }
            __syncthreads();
            const int r = tid >> 1, moff = (tid & 1) * 64;
            const __nv_bfloat16* src = sm + r * 136 + moff;
            __nv_bfloat16* dstrow = B2out + ((size_t)b * NPTS + nBase + r) * 512
                                    + plane * 256 + mBase + moff;
            #pragma unroll
            for (int q = 0; q < 8; q++)
                *(uint4*)(dstrow + q * 8) = *(const uint4*)(src + q * 8);
        }
    } else {
        float* Cb = Cout + (size_t)b * 256 * NPTS;
        #pragma unroll
        for (int i = 0; i < 4; i++) {
            const int r0 = mBase + wr * 64 + i * 16 + (lane >> 2);
            const float bv0 = bias[r0];
            const float bv1 = bias[r0 + 8];
            float* cr0 = Cb + (size_t)r0 * NPTS;
            float* cr1 = Cb + (size_t)(r0 + 8) * NPTS;
            #pragma unroll
            for (int jn = 0; jn < 4; jn++) {
                const int col = nBase + wc * 32 + jn * 8 + (lane & 3) * 2;
                float2 v0, v1;
                v0.x = fmaxf(acc[i][jn][0] + bv0, 0.0f);
                v0.y = fmaxf(acc[i][jn][1] + bv0, 0.0f);
                v1.x = fmaxf(acc[i][jn][2] + bv1, 0.0f);
                v1.y = fmaxf(acc[i][jn][3] + bv1, 0.0f);
                *(float2*)&cr0[col] = v0;
                *(float2*)&cr1[col] = v1;
            }
        }
    }
}

// ---------------- launch -----------------------------------------------------
extern "C" void kernel_launch(void* const* d_in, const int* in_sizes, int n_in,
                              void* d_out, int out_size)
{
    const float* unknown = (const float*)d_in[0];
    const float* known   = (const float*)d_in[1];
    const float* uf      = (const float*)d_in[2];
    const float* kf      = (const float*)d_in[3];
    const float* W1      = (const float*)d_in[4];
    const float* b1      = (const float*)d_in[5];
    const float* W2      = (const float*)d_in[6];
    const float* b2      = (const float*)d_in[7];
    float* out = (float*)d_out;

    float* p_kfT = nullptr;
    __nv_bfloat16 *p_B1 = nullptr, *p_B2 = nullptr, *p_W1s = nullptr, *p_W2s = nullptr;
    cudaGetSymbolAddress((void**)&p_kfT, g_kfT);
    cudaGetSymbolAddress((void**)&p_B1,  g_B1);
    cudaGetSymbolAddress((void**)&p_B2,  g_B2);
    cudaGetSymbolAddress((void**)&p_W1s, g_W1s);
    cudaGetSymbolAddress((void**)&p_W2s, g_W2s);

    three_nn_kernel<<<dim3(NPTS / 256, BATCH), 256>>>(unknown, known);
    kf_transpose_kernel<<<dim3(MPTS / 32, C2 / 32, BATCH), 256>>>(kf, p_kfT);
    interp_fused_kernel<<<dim3(NPTS / 32, BATCH), 256>>>(p_kfT, p_B1);
    uf_to_B1_kernel<<<dim3(NPTS / 32, BATCH), 256>>>(uf, p_B1);

    convert_w_kernel<<<(256 * 384 + 255) / 256, 256>>>(W1, p_W1s, 384);
    convert_w_kernel<<<(256 * 256 + 255) / 256, 256>>>(W2, p_W2s, 256);

    // layer 1: K'=1152, epilogue writes B2 (bf16 hi/lo, transposed)
    gemm_mma_kernel<<<dim3(NPTS / 128, 2, BATCH), 256>>>(
        p_W1s, b1, p_B1, nullptr, p_B2, 384);

    // layer 2: K'=768, fp32 output
    gemm_mma_kernel<<<dim3(NPTS / 128, 2, BATCH), 256>>>(
        p_W2s, b2, p_B2, out, nullptr, 256);
}

// round 6
// speedup vs baseline: 2.0482x; 1.0107x over previous
#include <cuda_runtime.h>
#include <cuda_bf16.h>
#include <math.h>
#include <stdint.h>

#define BATCH 8
#define NPTS  8192
#define MPTS  2048
#define C1    128
#define C2    256
#define CMID  256

// ---------------- scratch (device globals; no allocation allowed) ----------
__device__ int   g_idx[BATCH * NPTS * 3];
__device__ float g_w  [BATCH * NPTS * 3];
__device__ __align__(256) float g_kfT[BATCH * MPTS * C2];            // kf transposed [b][m][c]
__device__ __align__(256) __nv_bfloat16 g_B1 [BATCH * NPTS * 768];   // [b][n][hi384|lo384]
__device__ __align__(256) __nv_bfloat16 g_B2 [BATCH * NPTS * 512];   // [b][n][hi256|lo256]
__device__ __align__(256) __nv_bfloat16 g_W1s[256 * 768];            // [m][hi384|lo384]
__device__ __align__(256) __nv_bfloat16 g_W2s[256 * 512];            // [m][hi256|lo256]

// ---------------- helpers ----------------------------------------------------
__device__ __forceinline__ uint32_t smem_u32(const void* p) {
    uint32_t a;
    asm("{ .reg .u64 t; cvta.to.shared.u64 t, %1; cvt.u32.u64 %0, t; }" : "=r"(a) : "l"(p));
    return a;
}
#define CP_ASYNC16(dst, src) \
    asm volatile("cp.async.cg.shared.global [%0], [%1], 16;" :: "r"(dst), "l"(src))
#define CP_COMMIT() asm volatile("cp.async.commit_group;" ::: "memory")
#define CP_WAIT0()  asm volatile("cp.async.wait_group 0;" ::: "memory")
#define CP_WAIT1()  asm volatile("cp.async.wait_group 1;" ::: "memory")

#define LDSM4(r0, r1, r2, r3, addr) \
    asm volatile("ldmatrix.sync.aligned.m8n8.x4.shared.b16 {%0,%1,%2,%3}, [%4];" \
        : "=r"(r0), "=r"(r1), "=r"(r2), "=r"(r3) : "r"(addr))

#define MMA16816(d, a, b) \
    asm volatile("mma.sync.aligned.m16n8k16.row.col.f32.bf16.bf16.f32 " \
        "{%0,%1,%2,%3}, {%4,%5,%6,%7}, {%8,%9}, {%0,%1,%2,%3};" \
        : "+f"(d[0]), "+f"(d[1]), "+f"(d[2]), "+f"(d[3]) \
        : "r"(a[0]), "r"(a[1]), "r"(a[2]), "r"(a[3]), "r"(b[0]), "r"(b[1]))

__device__ __forceinline__ uint32_t pack_bf16(float a, float b) {
    __nv_bfloat16 x = __float2bfloat16(a);
    __nv_bfloat16 y = __float2bfloat16(b);
    return ((uint32_t)__bfloat16_as_ushort(y) << 16) | __bfloat16_as_ushort(x);
}

// ---------------- kernel 1: three_nn + weights ------------------------------
__global__ __launch_bounds__(256)
void three_nn_kernel(const float* __restrict__ unknown,
                     const float* __restrict__ known)
{
    __shared__ float4 sk[MPTS];
    const int b = blockIdx.y;
    const int j = blockIdx.x * blockDim.x + threadIdx.x;

    const float* kb = known + (size_t)b * MPTS * 3;
    for (int i = threadIdx.x; i < MPTS; i += blockDim.x) {
        float x = kb[i * 3 + 0], y = kb[i * 3 + 1], z = kb[i * 3 + 2];
        sk[i] = make_float4(x, y, z, x * x + y * y + z * z);
    }
    __syncthreads();

    const float* up = unknown + ((size_t)b * NPTS + j) * 3;
    const float ux = up[0], uy = up[1], uz = up[2];
    const float u2 = ux * ux + uy * uy + uz * uz;

    float d0 = 3.4e38f, d1 = 3.4e38f, d2v = 3.4e38f;
    int i0 = 0, i1 = 0, i2 = 0;

    #pragma unroll 4
    for (int i = 0; i < MPTS; i++) {
        float4 k = sk[i];
        float dot = ux * k.x + uy * k.y + uz * k.z;
        float d = u2 + k.w - 2.0f * dot;
        if (d < d2v) {                       // rare path: ~1 compare common case
            if (d < d0)      { d2v = d1; i2 = i1; d1 = d0; i1 = i0; d0 = d; i0 = i; }
            else if (d < d1) { d2v = d1; i2 = i1; d1 = d;  i1 = i; }
            else             { d2v = d;  i2 = i; }
        }
    }

    float s0 = sqrtf(fmaxf(d0, 0.0f));
    float s1 = sqrtf(fmaxf(d1, 0.0f));
    float s2 = sqrtf(fmaxf(d2v, 0.0f));
    float r0 = 1.0f / (s0 + 1e-8f);
    float r1 = 1.0f / (s1 + 1e-8f);
    float r2 = 1.0f / (s2 + 1e-8f);
    float rs = r0 + r1 + r2;

    const int o = ((b * NPTS) + j) * 3;
    g_idx[o + 0] = i0; g_idx[o + 1] = i1; g_idx[o + 2] = i2;
    g_w[o + 0] = r0 / rs; g_w[o + 1] = r1 / rs; g_w[o + 2] = r2 / rs;
}

// ---------------- kernel 2: transpose kf -> kfT [b][m][c] -------------------
__global__ __launch_bounds__(256)
void kf_transpose_kernel(const float* __restrict__ kf, float* __restrict__ kfT)
{
    __shared__ float s[32][33];
    const int b  = blockIdx.z;
    const int m0 = blockIdx.x * 32;
    const int c0 = blockIdx.y * 32;
    const int lane = threadIdx.x & 31, r = threadIdx.x >> 5;

    #pragma unroll
    for (int k = 0; k < 4; k++) {
        int c = r + k * 8;
        s[c][lane] = kf[((size_t)b * C2 + c0 + c) * MPTS + m0 + lane];
    }
    __syncthreads();
    #pragma unroll
    for (int k = 0; k < 4; k++) {
        int m = r + k * 8;
        kfT[((size_t)b * MPTS + m0 + m) * C2 + c0 + lane] = s[lane][m];
    }
}

// ---------------- kernel 3: fused interp + hi/lo convert -> B1[0..255] ------
__global__ __launch_bounds__(256)
void interp_fused_kernel(const float* __restrict__ kfT, __nv_bfloat16* __restrict__ B1)
{
    const int b    = blockIdx.y;
    const int lane = threadIdx.x & 31;
    const int warp = threadIdx.x >> 5;
    const int jbase = blockIdx.x * 32 + warp * 4;

    #pragma unroll
    for (int t = 0; t < 4; t++) {
        const int j = jbase + t;
        const int o = ((b * NPTS) + j) * 3;
        const int   i0 = g_idx[o + 0], i1 = g_idx[o + 1], i2 = g_idx[o + 2];
        const float w0 = g_w[o + 0],   w1 = g_w[o + 1],   w2 = g_w[o + 2];

        const float* r0 = kfT + ((size_t)b * MPTS + i0) * C2 + lane * 8;
        const float* r1 = kfT + ((size_t)b * MPTS + i1) * C2 + lane * 8;
        const float* r2 = kfT + ((size_t)b * MPTS + i2) * C2 + lane * 8;

        float4 a0 = *(const float4*)(r0);
        float4 a1 = *(const float4*)(r0 + 4);
        float4 b0 = *(const float4*)(r1);
        float4 b1 = *(const float4*)(r1 + 4);
        float4 c0 = *(const float4*)(r2);
        float4 c1 = *(const float4*)(r2 + 4);

        float v[8];
        v[0] = a0.x * w0 + b0.x * w1 + c0.x * w2;
        v[1] = a0.y * w0 + b0.y * w1 + c0.y * w2;
        v[2] = a0.z * w0 + b0.z * w1 + c0.z * w2;
        v[3] = a0.w * w0 + b0.w * w1 + c0.w * w2;
        v[4] = a1.x * w0 + b1.x * w1 + c1.x * w2;
        v[5] = a1.y * w0 + b1.y * w1 + c1.y * w2;
        v[6] = a1.z * w0 + b1.z * w1 + c1.z * w2;
        v[7] = a1.w * w0 + b1.w * w1 + c1.w * w2;

        uint4 hi, lo;
        float l[8];
        #pragma unroll
        for (int q = 0; q < 8; q++)
            l[q] = v[q] - __bfloat162float(__float2bfloat16(v[q]));
        hi.x = pack_bf16(v[0], v[1]); hi.y = pack_bf16(v[2], v[3]);
        hi.z = pack_bf16(v[4], v[5]); hi.w = pack_bf16(v[6], v[7]);
        lo.x = pack_bf16(l[0], l[1]); lo.y = pack_bf16(l[2], l[3]);
        lo.z = pack_bf16(l[4], l[5]); lo.w = pack_bf16(l[6], l[7]);

        __nv_bfloat16* row = B1 + ((size_t)b * NPTS + j) * 768;
        *(uint4*)(row + lane * 8)       = hi;
        *(uint4*)(row + 384 + lane * 8) = lo;
    }
}

// ---------------- kernel 4: uf -> B1[256..383] slices ------------------------
__global__ __launch_bounds__(256)
void uf_to_B1_kernel(const float* __restrict__ uf, __nv_bfloat16* __restrict__ B1)
{
    __shared__ float s[C1][33];
    const int b    = blockIdx.y;
    const int j0   = blockIdx.x * 32;
    const int lane = threadIdx.x & 31;
    const int warp = threadIdx.x >> 5;

    #pragma unroll
    for (int k = 0; k < 16; k++) {
        int c = warp + k * 8;
        s[c][lane] = uf[((size_t)b * C1 + c) * NPTS + j0 + lane];
    }
    __syncthreads();

    #pragma unroll
    for (int t = 0; t < 4; t++) {
        int jl = warp * 4 + t;
        __nv_bfloat16* row = B1 + ((size_t)b * NPTS + j0 + jl) * 768;
        #pragma unroll
        for (int q = 0; q < 2; q++) {
            int c = q * 64 + lane * 2;
            float v0 = s[c][jl], v1 = s[c + 1][jl];
            float l0 = v0 - __bfloat162float(__float2bfloat16(v0));
            float l1 = v1 - __bfloat162float(__float2bfloat16(v1));
            *(uint32_t*)(row + 256 + c) = pack_bf16(v0, v1);
            *(uint32_t*)(row + 640 + c) = pack_bf16(l0, l1);
        }
    }
}

// ---------------- weight split: W[256][K] -> Ws[256][hi K|lo K] -------------
__global__ __launch_bounds__(256)
void convert_w_kernel(const float* __restrict__ W, __nv_bfloat16* __restrict__ Ws, int K)
{
    int idx = blockIdx.x * 256 + threadIdx.x;
    if (idx >= 256 * K) return;
    int m = idx / K, k = idx - m * K;
    float w = W[idx];
    __nv_bfloat16 hi = __float2bfloat16(w);
    __nv_bfloat16 lo = __float2bfloat16(w - __bfloat162float(hi));
    __nv_bfloat16* row = Ws + (size_t)m * 2 * K;
    row[k] = hi; row[K + k] = lo;
}

// ---------------- mma.sync GEMM + fused epilogue -----------------------------
// A = Ws [256][2*Ksrc] (hi|lo); B = [b][n][2*Ksrc] (hi|lo).
// Per 32-k super-chunk: load Ahi,Alo,Bhi,Blo once; acc += Ahi.Bhi + Ahi.Blo + Alo.Bhi.
// CTA 128x128, 8 warps (warp 64x32), 3-stage cp.async pipeline, 1 sync/stage.
// Smem row = [hi 64B | lo 64B | 16B pad], pitch 144 (conflict-free ldmatrix).
#define TPITCH 144
#define TILEB  18432          // 128*144
#define STAGEB 36864          // A+B per stage
#define GSMEM  (3 * STAGEB)   // 110592

__global__ __launch_bounds__(256, 2)
void gemm_mma_kernel(const __nv_bfloat16* __restrict__ Ws,
                     const float* __restrict__ bias,
                     const __nv_bfloat16* __restrict__ Bmat,
                     float* __restrict__ Cout,
                     __nv_bfloat16* __restrict__ B2out,
                     int Ksrc)
{
    extern __shared__ __align__(16) char smem[];
    const uint32_t sb = smem_u32(smem);

    const int tid  = threadIdx.x;
    const int wid  = tid >> 5;
    const int lane = tid & 31;
    const int wr   = wid >> 2;
    const int wc   = wid & 3;

    const int K2 = 2 * Ksrc;
    const int S  = Ksrc >> 5;          // 32-k super-chunks

    const int b     = blockIdx.z;
    const int mBase = blockIdx.y * 128;
    const int nBase = blockIdx.x * 128;

    // per-thread load map: row = tid>>1, half(hi/lo) = tid&1, 4x16B each operand
    const int rowL = tid >> 1;
    const int half = tid & 1;
    const __nv_bfloat16* Arow = Ws + (size_t)(mBase + rowL) * K2 + half * Ksrc;
    const __nv_bfloat16* Brow = Bmat + ((size_t)b * NPTS + nBase + rowL) * K2 + half * Ksrc;
    const uint32_t dstA = sb + rowL * TPITCH + half * 64;
    const uint32_t dstB = dstA + TILEB;

    float acc[4][4][4];
    #pragma unroll
    for (int i = 0; i < 4; i++)
        #pragma unroll
        for (int j = 0; j < 4; j++)
            #pragma unroll
            for (int q = 0; q < 4; q++) acc[i][j][q] = 0.0f;

    #define LOAD_STAGE(sidx, buf) do {                                  \
        const __nv_bfloat16* _as = Arow + (sidx) * 32;                  \
        const __nv_bfloat16* _bs = Brow + (sidx) * 32;                  \
        uint32_t _da = dstA + (buf) * STAGEB;                           \
        uint32_t _db = dstB + (buf) * STAGEB;                           \
        CP_ASYNC16(_da,      _as);      CP_ASYNC16(_da + 16, _as + 8);  \
        CP_ASYNC16(_da + 32, _as + 16); CP_ASYNC16(_da + 48, _as + 24); \
        CP_ASYNC16(_db,      _bs);      CP_ASYNC16(_db + 16, _bs + 8);  \
        CP_ASYNC16(_db + 32, _bs + 16); CP_ASYNC16(_db + 48, _bs + 24); \
    } while (0)

    LOAD_STAGE(0, 0); CP_COMMIT();
    LOAD_STAGE(1, 1); CP_COMMIT();

    int buf = 0;
    for (int s = 0; s < S; s++) {
        if (s < S - 1) CP_WAIT1(); else CP_WAIT0();
        __syncthreads();
        if (s + 2 < S) {
            LOAD_STAGE(s + 2, (s + 2) % 3);
            CP_COMMIT();
        }

        const uint32_t aB = sb + buf * STAGEB;
        const uint32_t bB = aB + TILEB;

        #pragma unroll
        for (int kk = 0; kk < 2; kk++) {
            uint32_t a[4][4], bh[2][4], bl[2][4];
            uint32_t aAddr[4];
            #pragma unroll
            for (int jp = 0; jp < 2; jp++) {
                int row = wc * 32 + jp * 16 + (lane & 15);
                uint32_t addr = bB + row * TPITCH + kk * 32 + (lane >> 4) * 16;
                LDSM4(bh[jp][0], bh[jp][1], bh[jp][2], bh[jp][3], addr);
                LDSM4(bl[jp][0], bl[jp][1], bl[jp][2], bl[jp][3], addr + 64);
            }
            #pragma unroll
            for (int i = 0; i < 4; i++) {
                int row = wr * 64 + i * 16 + (lane & 15);
                aAddr[i] = aB + row * TPITCH + kk * 32 + (lane >> 4) * 16;
                LDSM4(a[i][0], a[i][1], a[i][2], a[i][3], aAddr[i]);   // hi
            }
            // Ahi*Bhi + Ahi*Blo
            #pragma unroll
            for (int i = 0; i < 4; i++) {
                #pragma unroll
                for (int jp = 0; jp < 2; jp++) {
                    uint32_t h0[2] = { bh[jp][0], bh[jp][2] };
                    uint32_t h1[2] = { bh[jp][1], bh[jp][3] };
                    uint32_t l0[2] = { bl[jp][0], bl[jp][2] };
                    uint32_t l1[2] = { bl[jp][1], bl[jp][3] };
                    MMA16816(acc[i][jp * 2 + 0], a[i], h0);
                    MMA16816(acc[i][jp * 2 + 1], a[i], h1);
                    MMA16816(acc[i][jp * 2 + 0], a[i], l0);
                    MMA16816(acc[i][jp * 2 + 1], a[i], l1);
                }
            }
            // Alo*Bhi
            #pragma unroll
            for (int i = 0; i < 4; i++)
                LDSM4(a[i][0], a[i][1], a[i][2], a[i][3], aAddr[i] + 64);  // lo
            #pragma unroll
            for (int i = 0; i < 4; i++) {
                #pragma unroll
                for (int jp = 0; jp < 2; jp++) {
                    uint32_t h0[2] = { bh[jp][0], bh[jp][2] };
                    uint32_t h1[2] = { bh[jp][1], bh[jp][3] };
                    MMA16816(acc[i][jp * 2 + 0], a[i], h0);
                    MMA16816(acc[i][jp * 2 + 1], a[i], h1);
                }
            }
        }
        buf = (buf + 1) % 3;
    }

    if (B2out) {
        // staged transpose to B2 [n][hi256|lo256], planes: 0=hi, 1=lo
        __nv_bfloat16* sm = (__nv_bfloat16*)smem;        // [128][136]
        #pragma unroll 1
        for (int plane = 0; plane < 2; plane++) {
            __syncthreads();
            #pragma unroll
            for (int i = 0; i < 4; i++) {
                const int ml0 = wr * 64 + i * 16 + (lane >> 2);
                const float bv0 = bias[mBase + ml0];
                const float bv1 = bias[mBase + ml0 + 8];
                #pragma unroll
                for (int jn = 0; jn < 4; jn++) {
                    const int nl = wc * 32 + jn * 8 + (lane & 3) * 2;
                    #pragma unroll
                    for (int q = 0; q < 4; q++) {
                        const int ml = ml0 + ((q >= 2) ? 8 : 0);
                        const int nn = nl + (q & 1);
                        const float v = fmaxf(acc[i][jn][q] + ((q >= 2) ? bv1 : bv0), 0.0f);
                        __nv_bfloat16 h = __float2bfloat16(v);
                        __nv_bfloat16 val = (plane == 0)
                            ? h : __float2bfloat16(v - __bfloat162float(h));
                        sm[nn * 136 + ml] = val;
                    }
                }
            }
            __syncthreads();
            const int r = tid >> 1, moff = (tid & 1) * 64;
            const __nv_bfloat16* src = sm + r * 136 + moff;
            __nv_bfloat16* dstrow = B2out + ((size_t)b * NPTS + nBase + r) * 512
                                    + plane * 256 + mBase + moff;
            #pragma unroll
            for (int q = 0; q < 8; q++)
                *(uint4*)(dstrow + q * 8) = *(const uint4*)(src + q * 8);
        }
    } else {
        float* Cb = Cout + (size_t)b * 256 * NPTS;
        #pragma unroll
        for (int i = 0; i < 4; i++) {
            const int r0 = mBase + wr * 64 + i * 16 + (lane >> 2);
            const float bv0 = bias[r0];
            const float bv1 = bias[r0 + 8];
            float* cr0 = Cb + (size_t)r0 * NPTS;
            float* cr1 = Cb + (size_t)(r0 + 8) * NPTS;
            #pragma unroll
            for (int jn = 0; jn < 4; jn++) {
                const int col = nBase + wc * 32 + jn * 8 + (lane & 3) * 2;
                float2 v0, v1;
                v0.x = fmaxf(acc[i][jn][0] + bv0, 0.0f);
                v0.y = fmaxf(acc[i][jn][1] + bv0, 0.0f);
                v1.x = fmaxf(acc[i][jn][2] + bv1, 0.0f);
                v1.y = fmaxf(acc[i][jn][3] + bv1, 0.0f);
                *(float2*)&cr0[col] = v0;
                *(float2*)&cr1[col] = v1;
            }
        }
    }
}

// ---------------- launch -----------------------------------------------------
extern "C" void kernel_launch(void* const* d_in, const int* in_sizes, int n_in,
                              void* d_out, int out_size)
{
    const float* unknown = (const float*)d_in[0];
    const float* known   = (const float*)d_in[1];
    const float* uf      = (const float*)d_in[2];
    const float* kf      = (const float*)d_in[3];
    const float* W1      = (const float*)d_in[4];
    const float* b1      = (const float*)d_in[5];
    const float* W2      = (const float*)d_in[6];
    const float* b2      = (const float*)d_in[7];
    float* out = (float*)d_out;

    float* p_kfT = nullptr;
    __nv_bfloat16 *p_B1 = nullptr, *p_B2 = nullptr, *p_W1s = nullptr, *p_W2s = nullptr;
    cudaGetSymbolAddress((void**)&p_kfT, g_kfT);
    cudaGetSymbolAddress((void**)&p_B1,  g_B1);
    cudaGetSymbolAddress((void**)&p_B2,  g_B2);
    cudaGetSymbolAddress((void**)&p_W1s, g_W1s);
    cudaGetSymbolAddress((void**)&p_W2s, g_W2s);

    cudaFuncSetAttribute(gemm_mma_kernel,
                         cudaFuncAttributeMaxDynamicSharedMemorySize, GSMEM);

    three_nn_kernel<<<dim3(NPTS / 256, BATCH), 256>>>(unknown, known);
    kf_transpose_kernel<<<dim3(MPTS / 32, C2 / 32, BATCH), 256>>>(kf, p_kfT);
    interp_fused_kernel<<<dim3(NPTS / 32, BATCH), 256>>>(p_kfT, p_B1);
    uf_to_B1_kernel<<<dim3(NPTS / 32, BATCH), 256>>>(uf, p_B1);

    convert_w_kernel<<<(256 * 384 + 255) / 256, 256>>>(W1, p_W1s, 384);
    convert_w_kernel<<<(256 * 256 + 255) / 256, 256>>>(W2, p_W2s, 256);

    // layer 1: Ksrc=384, epilogue writes B2 (bf16 hi/lo, transposed)
    gemm_mma_kernel<<<dim3(NPTS / 128, 2, BATCH), 256, GSMEM>>>(
        p_W1s, b1, p_B1, nullptr, p_B2, 384);

    // layer 2: Ksrc=256, fp32 output
    gemm_mma_kernel<<<dim3(NPTS / 128, 2, BATCH), 256, GSMEM>>>(
        p_W2s, b2, p_B2, out, nullptr, 256);
}

// round 7
// speedup vs baseline: 2.6604x; 1.2989x over previous
#include <cuda_runtime.h>
#include <cuda_fp16.h>
#include <math.h>
#include <stdint.h>

#define BATCH 8
#define NPTS  8192
#define MPTS  2048
#define C1    128
#define C2    256
#define CMID  256

// ---------------- scratch (device globals; no allocation allowed) ----------
__device__ int   g_idx[BATCH * NPTS * 3];
__device__ float g_w  [BATCH * NPTS * 3];
__device__ __align__(256) float g_kfT[BATCH * MPTS * C2];        // kf transposed [b][m][c]
__device__ __align__(256) __half g_B1 [BATCH * NPTS * 384];      // [b][n][384] fp16 (50MB)
__device__ __align__(256) __half g_B2 [BATCH * NPTS * 256];      // [b][n][256] fp16 (25MB)
__device__ __align__(256) __half g_W1s[256 * 768];               // [m][hi384|lo384]
__device__ __align__(256) __half g_W2s[256 * 512];               // [m][hi256|lo256]

// ---------------- helpers ----------------------------------------------------
__device__ __forceinline__ uint32_t smem_u32(const void* p) {
    uint32_t a;
    asm("{ .reg .u64 t; cvta.to.shared.u64 t, %1; cvt.u32.u64 %0, t; }" : "=r"(a) : "l"(p));
    return a;
}
#define CP_ASYNC16(dst, src) \
    asm volatile("cp.async.cg.shared.global [%0], [%1], 16;" :: "r"(dst), "l"(src))
#define CP_COMMIT() asm volatile("cp.async.commit_group;" ::: "memory")
#define CP_WAIT0()  asm volatile("cp.async.wait_group 0;" ::: "memory")
#define CP_WAIT1()  asm volatile("cp.async.wait_group 1;" ::: "memory")

#define LDSM4(r0, r1, r2, r3, addr) \
    asm volatile("ldmatrix.sync.aligned.m8n8.x4.shared.b16 {%0,%1,%2,%3}, [%4];" \
        : "=r"(r0), "=r"(r1), "=r"(r2), "=r"(r3) : "r"(addr))

#define MMAF16(d, a, b) \
    asm volatile("mma.sync.aligned.m16n8k16.row.col.f32.f16.f16.f32 " \
        "{%0,%1,%2,%3}, {%4,%5,%6,%7}, {%8,%9}, {%0,%1,%2,%3};" \
        : "+f"(d[0]), "+f"(d[1]), "+f"(d[2]), "+f"(d[3]) \
        : "r"(a[0]), "r"(a[1]), "r"(a[2]), "r"(a[3]), "r"(b[0]), "r"(b[1]))

__device__ __forceinline__ uint32_t pack_h2(float a, float b) {
    __half2 h = __floats2half2_rn(a, b);
    return *(uint32_t*)&h;
}

// ---------------- kernel 1: three_nn + weights ------------------------------
__global__ __launch_bounds__(256)
void three_nn_kernel(const float* __restrict__ unknown,
                     const float* __restrict__ known)
{
    __shared__ float4 sk[MPTS];
    const int b = blockIdx.y;
    const int j = blockIdx.x * blockDim.x + threadIdx.x;

    const float* kb = known + (size_t)b * MPTS * 3;
    for (int i = threadIdx.x; i < MPTS; i += blockDim.x) {
        float x = kb[i * 3 + 0], y = kb[i * 3 + 1], z = kb[i * 3 + 2];
        sk[i] = make_float4(x, y, z, x * x + y * y + z * z);
    }
    __syncthreads();

    const float* up = unknown + ((size_t)b * NPTS + j) * 3;
    const float ux = up[0], uy = up[1], uz = up[2];
    const float u2 = ux * ux + uy * uy + uz * uz;

    float d0 = 3.4e38f, d1 = 3.4e38f, d2v = 3.4e38f;
    int i0 = 0, i1 = 0, i2 = 0;

    #pragma unroll 4
    for (int i = 0; i < MPTS; i++) {
        float4 k = sk[i];
        float dot = ux * k.x + uy * k.y + uz * k.z;
        float d = u2 + k.w - 2.0f * dot;
        if (d < d2v) {
            if (d < d0)      { d2v = d1; i2 = i1; d1 = d0; i1 = i0; d0 = d; i0 = i; }
            else if (d < d1) { d2v = d1; i2 = i1; d1 = d;  i1 = i; }
            else             { d2v = d;  i2 = i; }
        }
    }

    float s0 = sqrtf(fmaxf(d0, 0.0f));
    float s1 = sqrtf(fmaxf(d1, 0.0f));
    float s2 = sqrtf(fmaxf(d2v, 0.0f));
    float r0 = 1.0f / (s0 + 1e-8f);
    float r1 = 1.0f / (s1 + 1e-8f);
    float r2 = 1.0f / (s2 + 1e-8f);
    float rs = r0 + r1 + r2;

    const int o = ((b * NPTS) + j) * 3;
    g_idx[o + 0] = i0; g_idx[o + 1] = i1; g_idx[o + 2] = i2;
    g_w[o + 0] = r0 / rs; g_w[o + 1] = r1 / rs; g_w[o + 2] = r2 / rs;
}

// ---------------- kernel 2: transpose kf -> kfT [b][m][c] -------------------
__global__ __launch_bounds__(256)
void kf_transpose_kernel(const float* __restrict__ kf, float* __restrict__ kfT)
{
    __shared__ float s[32][33];
    const int b  = blockIdx.z;
    const int m0 = blockIdx.x * 32;
    const int c0 = blockIdx.y * 32;
    const int lane = threadIdx.x & 31, r = threadIdx.x >> 5;

    #pragma unroll
    for (int k = 0; k < 4; k++) {
        int c = r + k * 8;
        s[c][lane] = kf[((size_t)b * C2 + c0 + c) * MPTS + m0 + lane];
    }
    __syncthreads();
    #pragma unroll
    for (int k = 0; k < 4; k++) {
        int m = r + k * 8;
        kfT[((size_t)b * MPTS + m0 + m) * C2 + c0 + lane] = s[lane][m];
    }
}

// ---------------- kernel 3: fused interp -> B1[0..255] (fp16) ---------------
__global__ __launch_bounds__(256)
void interp_fused_kernel(const float* __restrict__ kfT, __half* __restrict__ B1)
{
    const int b    = blockIdx.y;
    const int lane = threadIdx.x & 31;
    const int warp = threadIdx.x >> 5;
    const int jbase = blockIdx.x * 32 + warp * 4;

    #pragma unroll
    for (int t = 0; t < 4; t++) {
        const int j = jbase + t;
        const int o = ((b * NPTS) + j) * 3;
        const int   i0 = g_idx[o + 0], i1 = g_idx[o + 1], i2 = g_idx[o + 2];
        const float w0 = g_w[o + 0],   w1 = g_w[o + 1],   w2 = g_w[o + 2];

        const float* r0 = kfT + ((size_t)b * MPTS + i0) * C2 + lane * 8;
        const float* r1 = kfT + ((size_t)b * MPTS + i1) * C2 + lane * 8;
        const float* r2 = kfT + ((size_t)b * MPTS + i2) * C2 + lane * 8;

        float4 a0 = *(const float4*)(r0);
        float4 a1 = *(const float4*)(r0 + 4);
        float4 b0 = *(const float4*)(r1);
        float4 b1 = *(const float4*)(r1 + 4);
        float4 c0 = *(const float4*)(r2);
        float4 c1 = *(const float4*)(r2 + 4);

        float v[8];
        v[0] = a0.x * w0 + b0.x * w1 + c0.x * w2;
        v[1] = a0.y * w0 + b0.y * w1 + c0.y * w2;
        v[2] = a0.z * w0 + b0.z * w1 + c0.z * w2;
        v[3] = a0.w * w0 + b0.w * w1 + c0.w * w2;
        v[4] = a1.x * w0 + b1.x * w1 + c1.x * w2;
        v[5] = a1.y * w0 + b1.y * w1 + c1.y * w2;
        v[6] = a1.z * w0 + b1.z * w1 + c1.z * w2;
        v[7] = a1.w * w0 + b1.w * w1 + c1.w * w2;

        uint4 hv;
        hv.x = pack_h2(v[0], v[1]); hv.y = pack_h2(v[2], v[3]);
        hv.z = pack_h2(v[4], v[5]); hv.w = pack_h2(v[6], v[7]);

        *(uint4*)(B1 + ((size_t)b * NPTS + j) * 384 + lane * 8) = hv;
    }
}

// ---------------- kernel 4: uf -> B1[256..383] (fp16) ------------------------
__global__ __launch_bounds__(256)
void uf_to_B1_kernel(const float* __restrict__ uf, __half* __restrict__ B1)
{
    __shared__ float s[C1][33];
    const int b    = blockIdx.y;
    const int j0   = blockIdx.x * 32;
    const int lane = threadIdx.x & 31;
    const int warp = threadIdx.x >> 5;

    #pragma unroll
    for (int k = 0; k < 16; k++) {
        int c = warp + k * 8;
        s[c][lane] = uf[((size_t)b * C1 + c) * NPTS + j0 + lane];
    }
    __syncthreads();

    #pragma unroll
    for (int t = 0; t < 4; t++) {
        int jl = warp * 4 + t;
        __half* row = B1 + ((size_t)b * NPTS + j0 + jl) * 384 + 256;
        int c = lane * 4;
        uint2 out;
        out.x = pack_h2(s[c + 0][jl], s[c + 1][jl]);
        out.y = pack_h2(s[c + 2][jl], s[c + 3][jl]);
        *(uint2*)(row + c) = out;
    }
}

// ---------------- weight split: W[256][K] -> Ws[256][hi K|lo K] fp16 --------
__global__ __launch_bounds__(256)
void convert_w_kernel(const float* __restrict__ W, __half* __restrict__ Ws, int K)
{
    int idx = blockIdx.x * 256 + threadIdx.x;
    if (idx >= 256 * K) return;
    int m = idx / K, k = idx - m * K;
    float w = W[idx];
    __half hi = __float2half_rn(w);
    __half lo = __float2half_rn(w - __half2float(hi));
    __half* row = Ws + (size_t)m * 2 * K;
    row[k] = hi; row[K + k] = lo;
}

// ---------------- mma.sync GEMM + fused epilogue -----------------------------
// A = Ws [256][2K] fp16 (hi|lo); B = [b][n][K] fp16 single plane.
// C = Ahi.B + Alo.B  (2 MMA chains).
// CTA 128x128, 8 warps (warp 64x32), 3-stage cp.async pipeline.
// A smem row = [hi 64B | lo 64B | pad 16B] pitch 144; B row = 64B pitch 80.
#define PA 144
#define PB 80
#define TILE_A 18432          // 128*144
#define TILE_B 10240          // 128*80
#define STAGEB 28672
#define GSMEM  (3 * STAGEB)   // 86016

__global__ __launch_bounds__(256, 2)
void gemm_mma_kernel(const __half* __restrict__ Ws,
                     const float* __restrict__ bias,
                     const __half* __restrict__ Bmat,
                     float* __restrict__ Cout,
                     __half* __restrict__ B2out,
                     int Ksrc)
{
    extern __shared__ __align__(16) char smem[];
    const uint32_t sb = smem_u32(smem);

    const int tid  = threadIdx.x;
    const int wid  = tid >> 5;
    const int lane = tid & 31;
    const int wr   = wid >> 2;
    const int wc   = wid & 3;

    const int K2 = 2 * Ksrc;
    const int S  = Ksrc >> 5;

    const int b     = blockIdx.z;
    const int mBase = blockIdx.y * 128;
    const int nBase = blockIdx.x * 128;

    const int rowL = tid >> 1;
    const int half = tid & 1;
    const __half* Arow = Ws + (size_t)(mBase + rowL) * K2 + half * Ksrc;
    const __half* Brow = Bmat + ((size_t)b * NPTS + nBase + rowL) * Ksrc;
    const uint32_t dstA = sb + rowL * PA + half * 64;
    const uint32_t dstB = sb + TILE_A + rowL * PB + half * 32;

    float acc[4][4][4];
    #pragma unroll
    for (int i = 0; i < 4; i++)
        #pragma unroll
        for (int j = 0; j < 4; j++)
            #pragma unroll
            for (int q = 0; q < 4; q++) acc[i][j][q] = 0.0f;

    #define LOAD_STAGE(sidx, buf) do {                                   \
        const __half* _as = Arow + (sidx) * 32;                          \
        const __half* _bs = Brow + (sidx) * 32 + half * 16;              \
        uint32_t _da = dstA + (buf) * STAGEB;                            \
        uint32_t _db = dstB + (buf) * STAGEB;                            \
        CP_ASYNC16(_da,      _as);      CP_ASYNC16(_da + 16, _as + 8);   \
        CP_ASYNC16(_da + 32, _as + 16); CP_ASYNC16(_da + 48, _as + 24);  \
        CP_ASYNC16(_db,      _bs);      CP_ASYNC16(_db + 16, _bs + 8);   \
    } while (0)

    LOAD_STAGE(0, 0); CP_COMMIT();
    LOAD_STAGE(1, 1); CP_COMMIT();

    int buf = 0;
    for (int s = 0; s < S; s++) {
        if (s < S - 1) CP_WAIT1(); else CP_WAIT0();
        __syncthreads();
        if (s + 2 < S) {
            LOAD_STAGE(s + 2, (s + 2) % 3);
            CP_COMMIT();
        }

        const uint32_t aB = sb + buf * STAGEB;
        const uint32_t bB = aB + TILE_A;

        #pragma unroll
        for (int kk = 0; kk < 2; kk++) {
            uint32_t ah[4][4], al[4][4], bf[2][4];
            #pragma unroll
            for (int jp = 0; jp < 2; jp++) {
                int row = wc * 32 + jp * 16 + (lane & 15);
                uint32_t addr = bB + row * PB + kk * 32 + (lane >> 4) * 16;
                LDSM4(bf[jp][0], bf[jp][1], bf[jp][2], bf[jp][3], addr);
            }
            #pragma unroll
            for (int i = 0; i < 4; i++) {
                int row = wr * 64 + i * 16 + (lane & 15);
                uint32_t addr = aB + row * PA + kk * 32 + (lane >> 4) * 16;
                LDSM4(ah[i][0], ah[i][1], ah[i][2], ah[i][3], addr);
                LDSM4(al[i][0], al[i][1], al[i][2], al[i][3], addr + 64);
            }
            #pragma unroll
            for (int i = 0; i < 4; i++) {
                #pragma unroll
                for (int jp = 0; jp < 2; jp++) {
                    uint32_t b0[2] = { bf[jp][0], bf[jp][2] };
                    uint32_t b1[2] = { bf[jp][1], bf[jp][3] };
                    MMAF16(acc[i][jp * 2 + 0], ah[i], b0);
                    MMAF16(acc[i][jp * 2 + 1], ah[i], b1);
                    MMAF16(acc[i][jp * 2 + 0], al[i], b0);
                    MMAF16(acc[i][jp * 2 + 1], al[i], b1);
                }
            }
        }
        buf = (buf + 1) % 3;
    }

    if (B2out) {
        // staged transpose: B2 [n][256] fp16 single plane
        __half* sm = (__half*)smem;          // [128][136]
        __syncthreads();
        #pragma unroll
        for (int i = 0; i < 4; i++) {
            const int ml0 = wr * 64 + i * 16 + (lane >> 2);
            const float bv0 = bias[mBase + ml0];
            const float bv1 = bias[mBase + ml0 + 8];
            #pragma unroll
            for (int jn = 0; jn < 4; jn++) {
                const int nl = wc * 32 + jn * 8 + (lane & 3) * 2;
                #pragma unroll
                for (int q = 0; q < 4; q++) {
                    const int ml = ml0 + ((q >= 2) ? 8 : 0);
                    const int nn = nl + (q & 1);
                    const float v = fmaxf(acc[i][jn][q] + ((q >= 2) ? bv1 : bv0), 0.0f);
                    sm[nn * 136 + ml] = __float2half_rn(v);
                }
            }
        }
        __syncthreads();
        const int r = tid >> 1, moff = (tid & 1) * 64;
        const __half* src = sm + r * 136 + moff;
        __half* dstrow = B2out + ((size_t)b * NPTS + nBase + r) * 256 + mBase + moff;
        #pragma unroll
        for (int q = 0; q < 8; q++)
            *(uint4*)(dstrow + q * 8) = *(const uint4*)(src + q * 8);
    } else {
        float* Cb = Cout + (size_t)b * 256 * NPTS;
        #pragma unroll
        for (int i = 0; i < 4; i++) {
            const int r0 = mBase + wr * 64 + i * 16 + (lane >> 2);
            const float bv0 = bias[r0];
            const float bv1 = bias[r0 + 8];
            float* cr0 = Cb + (size_t)r0 * NPTS;
            float* cr1 = Cb + (size_t)(r0 + 8) * NPTS;
            #pragma unroll
            for (int jn = 0; jn < 4; jn++) {
                const int col = nBase + wc * 32 + jn * 8 + (lane & 3) * 2;
                float2 v0, v1;
                v0.x = fmaxf(acc[i][jn][0] + bv0, 0.0f);
                v0.y = fmaxf(acc[i][jn][1] + bv0, 0.0f);
                v1.x = fmaxf(acc[i][jn][2] + bv1, 0.0f);
                v1.y = fmaxf(acc[i][jn][3] + bv1, 0.0f);
                *(float2*)&cr0[col] = v0;
                *(float2*)&cr1[col] = v1;
            }
        }
    }
}

// ---------------- launch -----------------------------------------------------
extern "C" void kernel_launch(void* const* d_in, const int* in_sizes, int n_in,
                              void* d_out, int out_size)
{
    const float* unknown = (const float*)d_in[0];
    const float* known   = (const float*)d_in[1];
    const float* uf      = (const float*)d_in[2];
    const float* kf      = (const float*)d_in[3];
    const float* W1      = (const float*)d_in[4];
    const float* b1      = (const float*)d_in[5];
    const float* W2      = (const float*)d_in[6];
    const float* b2      = (const float*)d_in[7];
    float* out = (float*)d_out;

    float* p_kfT = nullptr;
    __half *p_B1 = nullptr, *p_B2 = nullptr, *p_W1s = nullptr, *p_W2s = nullptr;
    cudaGetSymbolAddress((void**)&p_kfT, g_kfT);
    cudaGetSymbolAddress((void**)&p_B1,  g_B1);
    cudaGetSymbolAddress((void**)&p_B2,  g_B2);
    cudaGetSymbolAddress((void**)&p_W1s, g_W1s);
    cudaGetSymbolAddress((void**)&p_W2s, g_W2s);

    cudaFuncSetAttribute(gemm_mma_kernel,
                         cudaFuncAttributeMaxDynamicSharedMemorySize, GSMEM);

    three_nn_kernel<<<dim3(NPTS / 256, BATCH), 256>>>(unknown, known);
    kf_transpose_kernel<<<dim3(MPTS / 32, C2 / 32, BATCH), 256>>>(kf, p_kfT);
    interp_fused_kernel<<<dim3(NPTS / 32, BATCH), 256>>>(p_kfT, p_B1);
    uf_to_B1_kernel<<<dim3(NPTS / 32, BATCH), 256>>>(uf, p_B1);

    convert_w_kernel<<<(256 * 384 + 255) / 256, 256>>>(W1, p_W1s, 384);
    convert_w_kernel<<<(256 * 256 + 255) / 256, 256>>>(W2, p_W2s, 256);

    // layer 1: Ksrc=384, epilogue writes B2 (fp16, transposed)
    gemm_mma_kernel<<<dim3(NPTS / 128, 2, BATCH), 256, GSMEM>>>(
        p_W1s, b1, p_B1, nullptr, p_B2, 384);

    // layer 2: Ksrc=256, fp32 output
    gemm_mma_kernel<<<dim3(NPTS / 128, 2, BATCH), 256, GSMEM>>>(
        p_W2s, b2, p_B2, out, nullptr, 256);
}

// round 8
// speedup vs baseline: 3.1010x; 1.1656x over previous
#include <cuda_runtime.h>
#include <cuda_fp16.h>
#include <math.h>
#include <stdint.h>

#define BATCH 8
#define NPTS  8192
#define MPTS  2048
#define C1    128
#define C2    256
#define CMID  256

// ---------------- scratch (device globals; no allocation allowed) ----------
__device__ int   g_idx[BATCH * NPTS * 3];
__device__ float g_w  [BATCH * NPTS * 3];
__device__ __align__(256) float g_kfT[BATCH * MPTS * C2];        // kf transposed [b][m][c]
__device__ __align__(256) __half g_B1 [BATCH * NPTS * 384];      // [b][n][384] fp16
__device__ __align__(256) __half g_B2 [BATCH * NPTS * 256];      // [b][n][256] fp16
__device__ __align__(256) __half g_W1s[256 * 768];               // [m][hi384|lo384]
__device__ __align__(256) __half g_W2s[256 * 512];               // [m][hi256|lo256]

// ---------------- helpers ----------------------------------------------------
__device__ __forceinline__ uint32_t smem_u32(const void* p) {
    uint32_t a;
    asm("{ .reg .u64 t; cvta.to.shared.u64 t, %1; cvt.u32.u64 %0, t; }" : "=r"(a) : "l"(p));
    return a;
}
#define CP_ASYNC16(dst, src) \
    asm volatile("cp.async.cg.shared.global [%0], [%1], 16;" :: "r"(dst), "l"(src))
#define CP_COMMIT() asm volatile("cp.async.commit_group;" ::: "memory")
#define CP_WAIT0()  asm volatile("cp.async.wait_group 0;" ::: "memory")
#define CP_WAIT1()  asm volatile("cp.async.wait_group 1;" ::: "memory")

#define LDSM4(r0, r1, r2, r3, addr) \
    asm volatile("ldmatrix.sync.aligned.m8n8.x4.shared.b16 {%0,%1,%2,%3}, [%4];" \
        : "=r"(r0), "=r"(r1), "=r"(r2), "=r"(r3) : "r"(addr))

#define MMAF16(d, a, b) \
    asm volatile("mma.sync.aligned.m16n8k16.row.col.f32.f16.f16.f32 " \
        "{%0,%1,%2,%3}, {%4,%5,%6,%7}, {%8,%9}, {%0,%1,%2,%3};" \
        : "+f"(d[0]), "+f"(d[1]), "+f"(d[2]), "+f"(d[3]) \
        : "r"(a[0]), "r"(a[1]), "r"(a[2]), "r"(a[3]), "r"(b[0]), "r"(b[1]))

__device__ __forceinline__ uint32_t pack_h2(float a, float b) {
    __half2 h = __floats2half2_rn(a, b);
    return *(uint32_t*)&h;
}

// ---------------- kernel 1: three_nn + weights (t-space compare) ------------
__global__ __launch_bounds__(256)
void three_nn_kernel(const float* __restrict__ unknown,
                     const float* __restrict__ known)
{
    __shared__ float4 sk[MPTS];
    const int b = blockIdx.y;
    const int j = blockIdx.x * blockDim.x + threadIdx.x;

    const float* kb = known + (size_t)b * MPTS * 3;
    for (int i = threadIdx.x; i < MPTS; i += blockDim.x) {
        float x = kb[i * 3 + 0], y = kb[i * 3 + 1], z = kb[i * 3 + 2];
        sk[i] = make_float4(x, y, z, x * x + y * y + z * z);
    }
    __syncthreads();

    const float* up = unknown + ((size_t)b * NPTS + j) * 3;
    const float ux = up[0], uy = up[1], uz = up[2];
    const float u2 = ux * ux + uy * uy + uz * uz;
    const float m2x = -2.0f * ux, m2y = -2.0f * uy, m2z = -2.0f * uz;

    // track t = k^2 - 2*dot ; d = t + u2 added at the end
    float t0 = 3.4e38f, t1 = 3.4e38f, t2v = 3.4e38f;
    int i0 = 0, i1 = 0, i2 = 0;

    #pragma unroll 4
    for (int i = 0; i < MPTS; i++) {
        float4 k = sk[i];
        float t = fmaf(m2x, k.x, k.w);
        t = fmaf(m2y, k.y, t);
        t = fmaf(m2z, k.z, t);
        if (t < t2v) {
            if (t < t0)      { t2v = t1; i2 = i1; t1 = t0; i1 = i0; t0 = t; i0 = i; }
            else if (t < t1) { t2v = t1; i2 = i1; t1 = t;  i1 = i; }
            else             { t2v = t;  i2 = i; }
        }
    }

    float s0 = sqrtf(fmaxf(t0 + u2, 0.0f));
    float s1 = sqrtf(fmaxf(t1 + u2, 0.0f));
    float s2 = sqrtf(fmaxf(t2v + u2, 0.0f));
    float r0 = 1.0f / (s0 + 1e-8f);
    float r1 = 1.0f / (s1 + 1e-8f);
    float r2 = 1.0f / (s2 + 1e-8f);
    float rs = r0 + r1 + r2;

    const int o = ((b * NPTS) + j) * 3;
    g_idx[o + 0] = i0; g_idx[o + 1] = i1; g_idx[o + 2] = i2;
    g_w[o + 0] = r0 / rs; g_w[o + 1] = r1 / rs; g_w[o + 2] = r2 / rs;
}

// ---------------- kernel 2: transpose kf -> kfT [b][m][c] -------------------
__global__ __launch_bounds__(256)
void kf_transpose_kernel(const float* __restrict__ kf, float* __restrict__ kfT)
{
    __shared__ float s[32][33];
    const int b  = blockIdx.z;
    const int m0 = blockIdx.x * 32;
    const int c0 = blockIdx.y * 32;
    const int lane = threadIdx.x & 31, r = threadIdx.x >> 5;

    #pragma unroll
    for (int k = 0; k < 4; k++) {
        int c = r + k * 8;
        s[c][lane] = kf[((size_t)b * C2 + c0 + c) * MPTS + m0 + lane];
    }
    __syncthreads();
    #pragma unroll
    for (int k = 0; k < 4; k++) {
        int m = r + k * 8;
        kfT[((size_t)b * MPTS + m0 + m) * C2 + c0 + lane] = s[lane][m];
    }
}

// ---------------- kernel 3: fused interp -> B1[0..255] (fp16) ---------------
__global__ __launch_bounds__(256)
void interp_fused_kernel(const float* __restrict__ kfT, __half* __restrict__ B1)
{
    const int b    = blockIdx.y;
    const int lane = threadIdx.x & 31;
    const int warp = threadIdx.x >> 5;
    const int jbase = blockIdx.x * 32 + warp * 4;

    #pragma unroll
    for (int t = 0; t < 4; t++) {
        const int j = jbase + t;
        const int o = ((b * NPTS) + j) * 3;
        const int   i0 = g_idx[o + 0], i1 = g_idx[o + 1], i2 = g_idx[o + 2];
        const float w0 = g_w[o + 0],   w1 = g_w[o + 1],   w2 = g_w[o + 2];

        const float* r0 = kfT + ((size_t)b * MPTS + i0) * C2 + lane * 8;
        const float* r1 = kfT + ((size_t)b * MPTS + i1) * C2 + lane * 8;
        const float* r2 = kfT + ((size_t)b * MPTS + i2) * C2 + lane * 8;

        float4 a0 = *(const float4*)(r0);
        float4 a1 = *(const float4*)(r0 + 4);
        float4 b0 = *(const float4*)(r1);
        float4 b1 = *(const float4*)(r1 + 4);
        float4 c0 = *(const float4*)(r2);
        float4 c1 = *(const float4*)(r2 + 4);

        float v[8];
        v[0] = a0.x * w0 + b0.x * w1 + c0.x * w2;
        v[1] = a0.y * w0 + b0.y * w1 + c0.y * w2;
        v[2] = a0.z * w0 + b0.z * w1 + c0.z * w2;
        v[3] = a0.w * w0 + b0.w * w1 + c0.w * w2;
        v[4] = a1.x * w0 + b1.x * w1 + c1.x * w2;
        v[5] = a1.y * w0 + b1.y * w1 + c1.y * w2;
        v[6] = a1.z * w0 + b1.z * w1 + c1.z * w2;
        v[7] = a1.w * w0 + b1.w * w1 + c1.w * w2;

        uint4 hv;
        hv.x = pack_h2(v[0], v[1]); hv.y = pack_h2(v[2], v[3]);
        hv.z = pack_h2(v[4], v[5]); hv.w = pack_h2(v[6], v[7]);

        *(uint4*)(B1 + ((size_t)b * NPTS + j) * 384 + lane * 8) = hv;
    }
}

// ---------------- kernel 4: uf -> B1[256..383] (fp16) ------------------------
__global__ __launch_bounds__(256)
void uf_to_B1_kernel(const float* __restrict__ uf, __half* __restrict__ B1)
{
    __shared__ float s[C1][33];
    const int b    = blockIdx.y;
    const int j0   = blockIdx.x * 32;
    const int lane = threadIdx.x & 31;
    const int warp = threadIdx.x >> 5;

    #pragma unroll
    for (int k = 0; k < 16; k++) {
        int c = warp + k * 8;
        s[c][lane] = uf[((size_t)b * C1 + c) * NPTS + j0 + lane];
    }
    __syncthreads();

    #pragma unroll
    for (int t = 0; t < 4; t++) {
        int jl = warp * 4 + t;
        __half* row = B1 + ((size_t)b * NPTS + j0 + jl) * 384 + 256;
        int c = lane * 4;
        uint2 out;
        out.x = pack_h2(s[c + 0][jl], s[c + 1][jl]);
        out.y = pack_h2(s[c + 2][jl], s[c + 3][jl]);
        *(uint2*)(row + c) = out;
    }
}

// ---------------- weight split: W[256][K] -> Ws[256][hi K|lo K] fp16 --------
__global__ __launch_bounds__(256)
void convert_w_kernel(const float* __restrict__ W, __half* __restrict__ Ws, int K)
{
    int idx = blockIdx.x * 256 + threadIdx.x;
    if (idx >= 256 * K) return;
    int m = idx / K, k = idx - m * K;
    float w = W[idx];
    __half hi = __float2half_rn(w);
    __half lo = __float2half_rn(w - __half2float(hi));
    __half* row = Ws + (size_t)m * 2 * K;
    row[k] = hi; row[K + k] = lo;
}

// ---------------- mma.sync GEMM + fused epilogue -----------------------------
// A = Ws [256][2K] fp16 (hi|lo); B = [b][n][K] fp16.  C = Ahi.B + Alo.B.
// CTA 128x128, 4 warps (warp 64x64), 3-stage cp.async pipeline, 2 CTA/SM.
// A smem row = [hi 64B | lo 64B | pad 16B] pitch 144; B row = 64B pitch 80.
#define PA 144
#define PB 80
#define TILE_A 18432          // 128*144
#define STAGEB 28672          // 18432 + 128*80
#define GSMEM  (3 * STAGEB)   // 86016

__global__ __launch_bounds__(128, 2)
void gemm_mma_kernel(const __half* __restrict__ Ws,
                     const float* __restrict__ bias,
                     const __half* __restrict__ Bmat,
                     float* __restrict__ Cout,
                     __half* __restrict__ B2out,
                     int Ksrc)
{
    extern __shared__ __align__(16) char smem[];
    const uint32_t sb = smem_u32(smem);

    const int tid  = threadIdx.x;
    const int wid  = tid >> 5;
    const int lane = tid & 31;
    const int wr   = wid >> 1;          // 0..1 (m half)
    const int wc   = wid & 1;           // 0..1 (n half)

    const int K2 = 2 * Ksrc;
    const int S  = Ksrc >> 5;

    const int b     = blockIdx.z;
    const int mBase = blockIdx.y * 128;
    const int nBase = blockIdx.x * 128;

    const __half* Abase = Ws + (size_t)mBase * K2;
    const __half* Bbase = Bmat + ((size_t)b * NPTS + nBase) * Ksrc;

    float acc[4][8][4];
    #pragma unroll
    for (int i = 0; i < 4; i++)
        #pragma unroll
        for (int j = 0; j < 8; j++)
            #pragma unroll
            for (int q = 0; q < 4; q++) acc[i][j][q] = 0.0f;

    // load maps (128 threads)
    // A: 128 rows x 8 chunks(16B): q<4 -> hi half, q>=4 -> lo half
    // B: 128 rows x 4 chunks(16B)
    #define LOAD_STAGE(sidx, buf) do {                                            \
        const int _s = (sidx);                                                    \
        const uint32_t _ab = sb + (buf) * STAGEB;                                 \
        const uint32_t _bb = _ab + TILE_A;                                        \
        _Pragma("unroll")                                                         \
        for (int _k = 0; _k < 8; _k++) {                                          \
            int _id = tid + _k * 128;                                             \
            int _r = _id >> 3, _q = _id & 7;                                      \
            const __half* _src = Abase + (size_t)_r * K2 + _s * 32                \
                                 + ((_q < 4) ? (_q * 8) : (Ksrc + (_q - 4) * 8)); \
            CP_ASYNC16(_ab + _r * PA + _q * 16, _src);                            \
        }                                                                         \
        _Pragma("unroll")                                                         \
        for (int _k = 0; _k < 4; _k++) {                                          \
            int _id = tid + _k * 128;                                             \
            int _r = _id >> 2, _q = _id & 3;                                      \
            CP_ASYNC16(_bb + _r * PB + _q * 16,                                   \
                       Bbase + (size_t)_r * Ksrc + _s * 32 + _q * 8);             \
        }                                                                         \
    } while (0)

    LOAD_STAGE(0, 0); CP_COMMIT();
    LOAD_STAGE(1, 1); CP_COMMIT();

    int buf = 0;
    for (int s = 0; s < S; s++) {
        if (s < S - 1) CP_WAIT1(); else CP_WAIT0();
        __syncthreads();
        if (s + 2 < S) {
            LOAD_STAGE(s + 2, (s + 2) % 3);
            CP_COMMIT();
        }

        const uint32_t aB = sb + buf * STAGEB;
        const uint32_t bB = aB + TILE_A;

        #pragma unroll
        for (int kk = 0; kk < 2; kk++) {
            uint32_t ah[4][4], al[4][4];
            #pragma unroll
            for (int i = 0; i < 4; i++) {
                int row = wr * 64 + i * 16 + (lane & 15);
                uint32_t addr = aB + row * PA + kk * 32 + (lane >> 4) * 16;
                LDSM4(ah[i][0], ah[i][1], ah[i][2], ah[i][3], addr);
                LDSM4(al[i][0], al[i][1], al[i][2], al[i][3], addr + 64);
            }
            #pragma unroll
            for (int jp = 0; jp < 4; jp++) {
                uint32_t bf[4];
                int row = wc * 64 + jp * 16 + (lane & 15);
                uint32_t addr = bB + row * PB + kk * 32 + (lane >> 4) * 16;
                LDSM4(bf[0], bf[1], bf[2], bf[3], addr);
                uint32_t b0[2] = { bf[0], bf[2] };
                uint32_t b1[2] = { bf[1], bf[3] };
                #pragma unroll
                for (int i = 0; i < 4; i++) {
                    MMAF16(acc[i][jp * 2 + 0], ah[i], b0);
                    MMAF16(acc[i][jp * 2 + 1], ah[i], b1);
                    MMAF16(acc[i][jp * 2 + 0], al[i], b0);
                    MMAF16(acc[i][jp * 2 + 1], al[i], b1);
                }
            }
        }
        buf = (buf + 1) % 3;
    }

    if (B2out) {
        // staged transpose: B2 [n][256] fp16 single plane
        __half* sm = (__half*)smem;          // [128 n][136 m]
        __syncthreads();
        #pragma unroll
        for (int i = 0; i < 4; i++) {
            const int ml0 = wr * 64 + i * 16 + (lane >> 2);
            const float bv0 = bias[mBase + ml0];
            const float bv1 = bias[mBase + ml0 + 8];
            #pragma unroll
            for (int jn = 0; jn < 8; jn++) {
                const int nl = wc * 64 + jn * 8 + (lane & 3) * 2;
                #pragma unroll
                for (int q = 0; q < 4; q++) {
                    const int ml = ml0 + ((q >= 2) ? 8 : 0);
                    const int nn = nl + (q & 1);
                    const float v = fmaxf(acc[i][jn][q] + ((q >= 2) ? bv1 : bv0), 0.0f);
                    sm[nn * 136 + ml] = __float2half_rn(v);
                }
            }
        }
        __syncthreads();
        const __half* src = sm + tid * 136;
        __half* dstrow = B2out + ((size_t)b * NPTS + nBase + tid) * 256 + mBase;
        #pragma unroll
        for (int q = 0; q < 16; q++)
            *(uint4*)(dstrow + q * 8) = *(const uint4*)(src + q * 8);
    } else {
        float* Cb = Cout + (size_t)b * 256 * NPTS;
        #pragma unroll
        for (int i = 0; i < 4; i++) {
            const int r0 = mBase + wr * 64 + i * 16 + (lane >> 2);
            const float bv0 = bias[r0];
            const float bv1 = bias[r0 + 8];
            float* cr0 = Cb + (size_t)r0 * NPTS;
            float* cr1 = Cb + (size_t)(r0 + 8) * NPTS;
            #pragma unroll
            for (int jn = 0; jn < 8; jn++) {
                const int col = nBase + wc * 64 + jn * 8 + (lane & 3) * 2;
                float2 v0, v1;
                v0.x = fmaxf(acc[i][jn][0] + bv0, 0.0f);
                v0.y = fmaxf(acc[i][jn][1] + bv0, 0.0f);
                v1.x = fmaxf(acc[i][jn][2] + bv1, 0.0f);
                v1.y = fmaxf(acc[i][jn][3] + bv1, 0.0f);
                *(float2*)&cr0[col] = v0;
                *(float2*)&cr1[col] = v1;
            }
        }
    }
}

// ---------------- launch -----------------------------------------------------
extern "C" void kernel_launch(void* const* d_in, const int* in_sizes, int n_in,
                              void* d_out, int out_size)
{
    const float* unknown = (const float*)d_in[0];
    const float* known   = (const float*)d_in[1];
    const float* uf      = (const float*)d_in[2];
    const float* kf      = (const float*)d_in[3];
    const float* W1      = (const float*)d_in[4];
    const float* b1      = (const float*)d_in[5];
    const float* W2      = (const float*)d_in[6];
    const float* b2      = (const float*)d_in[7];
    float* out = (float*)d_out;

    float* p_kfT = nullptr;
    __half *p_B1 = nullptr, *p_B2 = nullptr, *p_W1s = nullptr, *p_W2s = nullptr;
    cudaGetSymbolAddress((void**)&p_kfT, g_kfT);
    cudaGetSymbolAddress((void**)&p_B1,  g_B1);
    cudaGetSymbolAddress((void**)&p_B2,  g_B2);
    cudaGetSymbolAddress((void**)&p_W1s, g_W1s);
    cudaGetSymbolAddress((void**)&p_W2s, g_W2s);

    cudaFuncSetAttribute(gemm_mma_kernel,
                         cudaFuncAttributeMaxDynamicSharedMemorySize, GSMEM);

    three_nn_kernel<<<dim3(NPTS / 256, BATCH), 256>>>(unknown, known);
    kf_transpose_kernel<<<dim3(MPTS / 32, C2 / 32, BATCH), 256>>>(kf, p_kfT);
    interp_fused_kernel<<<dim3(NPTS / 32, BATCH), 256>>>(p_kfT, p_B1);
    uf_to_B1_kernel<<<dim3(NPTS / 32, BATCH), 256>>>(uf, p_B1);

    convert_w_kernel<<<(256 * 384 + 255) / 256, 256>>>(W1, p_W1s, 384);
    convert_w_kernel<<<(256 * 256 + 255) / 256, 256>>>(W2, p_W2s, 256);

    // layer 1: Ksrc=384, epilogue writes B2 (fp16, transposed)
    gemm_mma_kernel<<<dim3(NPTS / 128, 2, BATCH), 128, GSMEM>>>(
        p_W1s, b1, p_B1, nullptr, p_B2, 384);

    // layer 2: Ksrc=256, fp32 output
    gemm_mma_kernel<<<dim3(NPTS / 128, 2, BATCH), 128, GSMEM>>>(
        p_W2s, b2, p_B2, out, nullptr, 256);
}